// round 4
// baseline (speedup 1.0000x reference)
#include <cuda_runtime.h>

#define SQ 2048
#define BB 2
#define EE 1024
#define HH 16
#define DD 64
#define MM (SQ*BB)              // 4096 rows (s,b)
#define SCALE 0.125f            // 64^-0.5
#define RMS_EPS 1e-6f

// ---------------- scratch (device globals: no runtime allocation) ----------
__device__ float g_Q[(size_t)BB*HH*SQ*DD];   // [b][h][s][d]
__device__ float g_K[(size_t)BB*HH*SQ*DD];
__device__ float g_V[(size_t)BB*HH*SQ*DD];
__device__ float g_A[(size_t)MM*EE];         // attention out, [s][b][e]

// ---------------- GEMM: C = A * W^T (+bias) --------------------------------
// A: [MM, EE] row-major.  W: [EE, EE] row-major (row n holds k-vector).
// MODE 0: C[m][n] row-major to out (no bias).
// MODE 1: scatter to BHSD layout: out[((b*HH+h)*SQ+s)*DD+d], with bias[n].
template<int MODE>
__global__ __launch_bounds__(256, 2)
void gemm_nt(const float* __restrict__ A, const float* __restrict__ W,
             const float* __restrict__ bias, float* __restrict__ out)
{
    __shared__ float As[8][128];
    __shared__ float Bs[8][128];
    const int tid = threadIdx.x;
    const int tx = tid & 15, ty = tid >> 4;
    const int m0 = blockIdx.y * 128;
    const int n0 = blockIdx.x * 128;
    const int lrow = tid >> 1;          // 0..127
    const int lseg = (tid & 1) * 4;     // 0 or 4
    const float* Ap = A + (size_t)(m0 + lrow) * EE + lseg;
    const float* Wp = W + (size_t)(n0 + lrow) * EE + lseg;

    float acc[8][8];
#pragma unroll
    for (int i = 0; i < 8; i++)
#pragma unroll
        for (int j = 0; j < 8; j++) acc[i][j] = 0.f;

    for (int k0 = 0; k0 < EE; k0 += 8) {
        float4 av = *(const float4*)(Ap + k0);
        float4 wv = *(const float4*)(Wp + k0);
        As[lseg+0][lrow] = av.x; As[lseg+1][lrow] = av.y;
        As[lseg+2][lrow] = av.z; As[lseg+3][lrow] = av.w;
        Bs[lseg+0][lrow] = wv.x; Bs[lseg+1][lrow] = wv.y;
        Bs[lseg+2][lrow] = wv.z; Bs[lseg+3][lrow] = wv.w;
        __syncthreads();
#pragma unroll
        for (int kk = 0; kk < 8; kk++) {
            float a[8], b[8];
            *(float4*)(a)   = *(const float4*)&As[kk][ty*4];
            *(float4*)(a+4) = *(const float4*)&As[kk][64 + ty*4];
            *(float4*)(b)   = *(const float4*)&Bs[kk][tx*4];
            *(float4*)(b+4) = *(const float4*)&Bs[kk][64 + tx*4];
#pragma unroll
            for (int i = 0; i < 8; i++)
#pragma unroll
                for (int j = 0; j < 8; j++)
                    acc[i][j] += a[i] * b[j];
        }
        __syncthreads();
    }

#pragma unroll
    for (int i = 0; i < 8; i++) {
        int m = m0 + ((i < 4) ? (ty*4 + i) : (64 + ty*4 + (i - 4)));
#pragma unroll
        for (int j = 0; j < 8; j++) {
            int n = n0 + ((j < 4) ? (tx*4 + j) : (64 + tx*4 + (j - 4)));
            float v = acc[i][j];
            if (MODE == 1) {
                v += bias[n];
                int s = m >> 1, b = m & 1;        // BB == 2
                int h = n >> 6, d = n & 63;       // DD == 64
                out[(((size_t)(b*HH + h))*SQ + s)*DD + d] = v;
            } else {
                out[(size_t)m*EE + n] = v;
            }
        }
    }
}

// ---------------- RoPE (in-place on g_Q, g_K) -------------------------------
__global__ __launch_bounds__(256)
void rope_kernel(const float* __restrict__ cosT, const float* __restrict__ sinT)
{
    int gid = blockIdx.x * 256 + threadIdx.x;   // BB*HH*SQ*32 threads
    int d   = gid & 31;
    int row = gid >> 5;                          // bh*SQ + s
    int s   = row & (SQ - 1);
    size_t base = (size_t)row * DD;
    float c1 = cosT[s*DD + d],      s1 = sinT[s*DD + d];
    float c2 = cosT[s*DD + d + 32], s2 = sinT[s*DD + d + 32];

    float q1 = g_Q[base + d], q2 = g_Q[base + d + 32];
    g_Q[base + d]      = q1*c1 - q2*s1;
    g_Q[base + d + 32] = q2*c2 + q1*s2;

    float k1 = g_K[base + d], k2 = g_K[base + d + 32];
    g_K[base + d]      = k1*c1 - k2*s1;
    g_K[base + d + 32] = k2*c2 + k1*s2;
}

// ---------------- Flash attention (causal), fp32 ----------------------------
#define AT_PAD 68
#define AT_SMEM (3 * 64 * AT_PAD * 4)   // 52224 bytes

__global__ __launch_bounds__(256)
void attn_kernel()
{
    extern __shared__ float sm[];
    float* Qs = sm;                      // [64][AT_PAD], pre-scaled Q
    float* KP = sm + 64*AT_PAD;          // [64][AT_PAD], K tile then P tile
    float* Vs = sm + 2*64*AT_PAD;        // [64][AT_PAD]

    const int tid = threadIdx.x;
    const int tx  = tid & 15, ty = tid >> 4;
    const int bh  = blockIdx.y;                       // b*HH + h
    const int qi  = gridDim.x - 1 - blockIdx.x;       // heavy tiles first
    const int s0  = qi * 64;

    const float* Qg = g_Q + ((size_t)bh*SQ + s0) * DD;
    const float* Kg = g_K + (size_t)bh*SQ*DD;
    const float* Vg = g_V + (size_t)bh*SQ*DD;

    // load + pre-scale Q tile
#pragma unroll
    for (int l = 0; l < 4; l++) {
        int v = tid + 256*l;
        int r = v >> 4, seg = (v & 15) * 4;
        float4 q = *(const float4*)(Qg + (size_t)r*DD + seg);
        float4 qs = {q.x*SCALE, q.y*SCALE, q.z*SCALE, q.w*SCALE};
        *(float4*)&Qs[r*AT_PAD + seg] = qs;
    }

    float m_i[4], l_i[4], o[4][4];
#pragma unroll
    for (int i = 0; i < 4; i++) {
        m_i[i] = -1e30f; l_i[i] = 0.f;
#pragma unroll
        for (int j = 0; j < 4; j++) o[i][j] = 0.f;
    }

    for (int jt = 0; jt <= qi; jt++) {
        const int t0 = jt * 64;
        __syncthreads();   // prev P·V done (and Q load on first iter)
#pragma unroll
        for (int l = 0; l < 4; l++) {
            int v = tid + 256*l;
            int r = v >> 4, seg = (v & 15) * 4;
            *(float4*)&KP[r*AT_PAD + seg] = *(const float4*)(Kg + (size_t)(t0 + r)*DD + seg);
            *(float4*)&Vs[r*AT_PAD + seg] = *(const float4*)(Vg + (size_t)(t0 + r)*DD + seg);
        }
        __syncthreads();

        // scores: sc[i][j] = (SCALE*q_row_i) . k_row_j
        float sc[4][4];
#pragma unroll
        for (int i = 0; i < 4; i++)
#pragma unroll
            for (int j = 0; j < 4; j++) sc[i][j] = 0.f;

#pragma unroll
        for (int d4 = 0; d4 < DD; d4 += 4) {
            float4 kv[4];
#pragma unroll
            for (int j = 0; j < 4; j++)
                kv[j] = *(const float4*)&KP[(4*tx + j)*AT_PAD + d4];
#pragma unroll
            for (int i = 0; i < 4; i++) {
                float4 qv = *(const float4*)&Qs[(4*ty + i)*AT_PAD + d4];
#pragma unroll
                for (int j = 0; j < 4; j++)
                    sc[i][j] += qv.x*kv[j].x + qv.y*kv[j].y + qv.z*kv[j].z + qv.w*kv[j].w;
            }
        }

        if (jt == qi) {   // diagonal tile: causal mask
#pragma unroll
            for (int i = 0; i < 4; i++) {
                int r = s0 + 4*ty + i;
#pragma unroll
                for (int j = 0; j < 4; j++) {
                    int t = t0 + 4*tx + j;
                    if (t > r) sc[i][j] = -1e30f;
                }
            }
        }

        // online softmax
        float p[4][4];
#pragma unroll
        for (int i = 0; i < 4; i++) {
            float mx = fmaxf(fmaxf(sc[i][0], sc[i][1]), fmaxf(sc[i][2], sc[i][3]));
#pragma unroll
            for (int w = 1; w < 16; w <<= 1)
                mx = fmaxf(mx, __shfl_xor_sync(0xffffffffu, mx, w));
            float mnew = fmaxf(m_i[i], mx);
            float corr = __expf(m_i[i] - mnew);
            float ps = 0.f;
#pragma unroll
            for (int j = 0; j < 4; j++) { p[i][j] = __expf(sc[i][j] - mnew); ps += p[i][j]; }
#pragma unroll
            for (int w = 1; w < 16; w <<= 1)
                ps += __shfl_xor_sync(0xffffffffu, ps, w);
            l_i[i] = l_i[i]*corr + ps;
            m_i[i] = mnew;
#pragma unroll
            for (int j = 0; j < 4; j++) o[i][j] *= corr;
        }

        __syncthreads();   // all K reads done before overwriting with P
#pragma unroll
        for (int i = 0; i < 4; i++) {
            float4 pv = {p[i][0], p[i][1], p[i][2], p[i][3]};
            *(float4*)&KP[(4*ty + i)*AT_PAD + 4*tx] = pv;
        }
        __syncthreads();

        // O += P * V
#pragma unroll
        for (int t4 = 0; t4 < 64; t4 += 4) {
            float4 vr[4];
#pragma unroll
            for (int tt = 0; tt < 4; tt++)
                vr[tt] = *(const float4*)&Vs[(t4 + tt)*AT_PAD + 4*tx];
#pragma unroll
            for (int i = 0; i < 4; i++) {
                float4 pv = *(const float4*)&KP[(4*ty + i)*AT_PAD + t4];
                o[i][0] += pv.x*vr[0].x + pv.y*vr[1].x + pv.z*vr[2].x + pv.w*vr[3].x;
                o[i][1] += pv.x*vr[0].y + pv.y*vr[1].y + pv.z*vr[2].y + pv.w*vr[3].y;
                o[i][2] += pv.x*vr[0].z + pv.y*vr[1].z + pv.z*vr[2].z + pv.w*vr[3].z;
                o[i][3] += pv.x*vr[0].w + pv.y*vr[1].w + pv.z*vr[2].w + pv.w*vr[3].w;
            }
        }
    }

    // normalize + write to [s][b][e]
    const int b = bh >> 4, h = bh & 15;
#pragma unroll
    for (int i = 0; i < 4; i++) {
        int s = s0 + 4*ty + i;
        float inv = 1.f / l_i[i];
        float4 ov = {o[i][0]*inv, o[i][1]*inv, o[i][2]*inv, o[i][3]*inv};
        *(float4*)&g_A[((size_t)s*BB + b)*EE + h*DD + 4*tx] = ov;
    }
}

// ---------------- RMSNorm (in-place on g_A) ---------------------------------
__global__ __launch_bounds__(256)
void rmsnorm_kernel(const float* __restrict__ w)
{
    const int r = blockIdx.x;
    float* a = g_A + (size_t)r * EE;
    const int tid = threadIdx.x;
    float v[4];
    float ss = 0.f;
#pragma unroll
    for (int l = 0; l < 4; l++) { v[l] = a[tid + 256*l]; ss += v[l]*v[l]; }
#pragma unroll
    for (int ofs = 16; ofs; ofs >>= 1) ss += __shfl_xor_sync(0xffffffffu, ss, ofs);
    __shared__ float red[8];
    if ((tid & 31) == 0) red[tid >> 5] = ss;
    __syncthreads();
    float tot = 0.f;
#pragma unroll
    for (int i = 0; i < 8; i++) tot += red[i];
    float rstd = rsqrtf(tot * (1.f / EE) + RMS_EPS);
#pragma unroll
    for (int l = 0; l < 4; l++) {
        int e = tid + 256*l;
        a[e] = v[l] * rstd * w[e];
    }
}

// ---------------- launch -----------------------------------------------------
extern "C" void kernel_launch(void* const* d_in, const int* in_sizes, int n_in,
                              void* d_out, int out_size)
{
    const float* x    = (const float*)d_in[0];
    // d_in[1] = attn_mask (pure causal, implemented analytically)
    const float* cosT = (const float*)d_in[2];
    const float* sinT = (const float*)d_in[3];
    const float* Wq   = (const float*)d_in[4];
    const float* bq   = (const float*)d_in[5];
    const float* Wk   = (const float*)d_in[6];
    const float* bk   = (const float*)d_in[7];
    const float* Wv   = (const float*)d_in[8];
    const float* bv   = (const float*)d_in[9];
    const float* Wo   = (const float*)d_in[10];
    const float* nw   = (const float*)d_in[11];

    float *pQ, *pK, *pV, *pA;
    cudaGetSymbolAddress((void**)&pQ, g_Q);
    cudaGetSymbolAddress((void**)&pK, g_K);
    cudaGetSymbolAddress((void**)&pV, g_V);
    cudaGetSymbolAddress((void**)&pA, g_A);

    dim3 ggrid(EE/128, MM/128);
    gemm_nt<1><<<ggrid, 256>>>(x, Wq, bq, pQ);
    gemm_nt<1><<<ggrid, 256>>>(x, Wk, bk, pK);
    gemm_nt<1><<<ggrid, 256>>>(x, Wv, bv, pV);

    rope_kernel<<<(BB*HH*SQ*32)/256, 256>>>(cosT, sinT);

    cudaFuncSetAttribute(attn_kernel, cudaFuncAttributeMaxDynamicSharedMemorySize, AT_SMEM);
    attn_kernel<<<dim3(SQ/64, BB*HH), 256, AT_SMEM>>>();

    rmsnorm_kernel<<<MM, 256>>>(nw);

    gemm_nt<0><<<ggrid, 256>>>(pA, Wo, nullptr, (float*)d_out);
}

// round 10
// speedup vs baseline: 1.5054x; 1.5054x over previous
#include <cuda_runtime.h>
#include <cuda_bf16.h>
#include <cstdint>

#define SQ 2048
#define BB 2
#define EE 1024
#define HH 16
#define DD 64
#define MM (SQ*BB)              // 4096 rows (s,b)
#define SCALE 0.125f            // 64^-0.5
#define RMS_EPS 1e-6f

// ---------------- scratch (device globals: no runtime allocation) ----------
__device__ float g_Q[(size_t)BB*HH*SQ*DD];   // [b][h][s][d]
__device__ float g_K[(size_t)BB*HH*SQ*DD];
__device__ float g_V[(size_t)BB*HH*SQ*DD];
__device__ float g_A[(size_t)MM*EE];         // attention out, [s][b][e]
__device__ __nv_bfloat16 g_xhi[(size_t)MM*EE];
__device__ __nv_bfloat16 g_xlo[(size_t)MM*EE];
__device__ __nv_bfloat16 g_whi[(size_t)EE*EE];
__device__ __nv_bfloat16 g_wlo[(size_t)EE*EE];

// ---------------- PTX helpers (plain sm_103-safe: no 'a' features) ----------
__device__ __forceinline__ uint32_t smem_u32(const void* p) {
    uint32_t a;
    asm("{ .reg .u64 t; cvta.to.shared.u64 t, %1; cvt.u32.u64 %0, t; }"
        : "=r"(a) : "l"(p));
    return a;
}

__device__ __forceinline__ void cp_async16(uint32_t smem, const void* g) {
    asm volatile("cp.async.cg.shared.global [%0], [%1], 16;"
                 :: "r"(smem), "l"(g) : "memory");
}
#define CP_COMMIT() asm volatile("cp.async.commit_group;" ::: "memory")
#define CP_WAIT(n)  asm volatile("cp.async.wait_group %0;" :: "n"(n) : "memory")

__device__ __forceinline__ void ldm_x4(uint32_t* r, uint32_t addr) {
    asm volatile("ldmatrix.sync.aligned.m8n8.x4.shared.b16 {%0,%1,%2,%3}, [%4];"
                 : "=r"(r[0]), "=r"(r[1]), "=r"(r[2]), "=r"(r[3]) : "r"(addr));
}
__device__ __forceinline__ void ldm_x2(uint32_t* r, uint32_t addr) {
    asm volatile("ldmatrix.sync.aligned.m8n8.x2.shared.b16 {%0,%1}, [%2];"
                 : "=r"(r[0]), "=r"(r[1]) : "r"(addr));
}

__device__ __forceinline__ void mma16816(float* c, const uint32_t* a, const uint32_t* b) {
    asm volatile(
        "mma.sync.aligned.m16n8k16.row.col.f32.bf16.bf16.f32 "
        "{%0,%1,%2,%3}, {%4,%5,%6,%7}, {%8,%9}, {%0,%1,%2,%3};"
        : "+f"(c[0]), "+f"(c[1]), "+f"(c[2]), "+f"(c[3])
        : "r"(a[0]), "r"(a[1]), "r"(a[2]), "r"(a[3]), "r"(b[0]), "r"(b[1]));
}

#define SWZ64(off) ((off) ^ (((off) >> 3) & 0x30))

// ---------------- fp32 -> (hi, lo) bf16 split -------------------------------
__global__ __launch_bounds__(256)
void cvt_hilo(const float* __restrict__ x, __nv_bfloat16* __restrict__ hi,
              __nv_bfloat16* __restrict__ lo, int n4)
{
    int i = blockIdx.x * 256 + threadIdx.x;
    if (i >= n4) return;
    float4 v = ((const float4*)x)[i];
    float vv[4] = {v.x, v.y, v.z, v.w};
    __nv_bfloat16 h[4], l[4];
#pragma unroll
    for (int j = 0; j < 4; j++) {
        h[j] = __float2bfloat16(vv[j]);
        l[j] = __float2bfloat16(vv[j] - __bfloat162float(h[j]));
    }
    __nv_bfloat162 h01, h23, l01, l23;
    h01.x = h[0]; h01.y = h[1]; h23.x = h[2]; h23.y = h[3];
    l01.x = l[0]; l01.y = l[1]; l23.x = l[2]; l23.y = l[3];
    uint2 uh, ul;
    uh.x = *(uint32_t*)&h01; uh.y = *(uint32_t*)&h23;
    ul.x = *(uint32_t*)&l01; ul.y = *(uint32_t*)&l23;
    ((uint2*)hi)[i] = uh;
    ((uint2*)lo)[i] = ul;
}

// ---------------- mma.sync GEMM: C = A * W^T (+bias) ------------------------
// A (hi/lo): [MM, EE] bf16 row-major.  W (hi/lo): [EE, EE] bf16 row-major.
// C += Ahi*Bhi^T + Ahi*Blo^T + Alo*Bhi^T  (fp32 accumulate in registers)
// CTA tile 128x128, 8 warps (2x4), warp tile 64x32 = 4x4 mma tiles.
// K chunk = 32, 32 chunks (full K=1024), cp.async double buffer.
// SW64-swizzled smem for ldmatrix.
// MODE 0: C[m][n] row-major (no bias).  MODE 1: scatter to BHSD with bias[n].
#define G_STAGE 32768                   // 4 matrices x 128 rows x 64B
#define G_SMEM  (2 * G_STAGE)

template<int MODE>
__global__ __launch_bounds__(256, 1)
void gemm_mma(const __nv_bfloat16* __restrict__ Ahi, const __nv_bfloat16* __restrict__ Alo,
              const __nv_bfloat16* __restrict__ Bhi, const __nv_bfloat16* __restrict__ Blo,
              const float* __restrict__ bias, float* __restrict__ out)
{
    extern __shared__ char dsm[];
    const uint32_t sb = smem_u32(dsm);
    const int tid  = threadIdx.x;
    const int wid  = tid >> 5, lane = tid & 31;
    const int wm   = wid >> 2, wn = wid & 3;      // warp grid 2x4
    const int m0   = blockIdx.y * 128;
    const int n0   = blockIdx.x * 128;

    float acc[4][4][4];
#pragma unroll
    for (int i = 0; i < 4; i++)
#pragma unroll
        for (int j = 0; j < 4; j++)
#pragma unroll
            for (int k = 0; k < 4; k++) acc[i][j][k] = 0.f;

    // lane-invariant pieces of ldmatrix addresses
    const int a_row = (lane & 15);            // within 16-row tile
    const int a_u   = (lane >> 4);            // 0/1 -> extra 16B in k
    const int b_row = (lane & 7);
    const int b_u   = ((lane & 15) >> 3);

    // cp.async issue of one 32-wide k chunk into stage st
    auto issue = [&](int ck, int st) {
        const uint32_t base = sb + st * G_STAGE;
#pragma unroll
        for (int i = 0; i < 8; i++) {
            const int t   = i >> 1;                       // matrix 0..3
            const int cid = (i & 1) * 256 + tid;          // 0..511
            const int row = cid >> 2, u = cid & 3;
            const __nv_bfloat16* src = (t == 0) ? Ahi : (t == 1) ? Alo
                                     : (t == 2) ? Bhi : Blo;
            const int r0 = (t < 2) ? m0 : n0;
            const char* g = (const char*)(src + (size_t)(r0 + row) * EE + ck * 32) + u * 16;
            uint32_t off = (uint32_t)(row * 64 + u * 16);
            cp_async16(base + t * 8192 + SWZ64(off), g);
        }
    };

    issue(0, 0); CP_COMMIT();

    for (int ck = 0; ck < 32; ck++) {               // full K: 32 chunks of 32
        const int st = ck & 1;
        if (ck < 31) { issue(ck + 1, st ^ 1); CP_COMMIT(); CP_WAIT(1); }
        else         { CP_WAIT(0); }
        __syncthreads();

        const uint32_t bAhi = sb + st * G_STAGE;
        const uint32_t bAlo = bAhi + 8192;
        const uint32_t bBhi = bAhi + 16384;
        const uint32_t bBlo = bAhi + 24576;

#pragma unroll
        for (int ks = 0; ks < 2; ks++) {
            uint32_t ah[4][4], al[4][4], bh[4][2], bl[4][2];
#pragma unroll
            for (int mt = 0; mt < 4; mt++) {
                uint32_t off = (uint32_t)((wm * 64 + mt * 16 + a_row) * 64
                                          + (ks * 2 + a_u) * 16);
                off = SWZ64(off);
                ldm_x4(ah[mt], bAhi + off);
                ldm_x4(al[mt], bAlo + off);
            }
#pragma unroll
            for (int nt = 0; nt < 4; nt++) {
                uint32_t off = (uint32_t)((wn * 32 + nt * 8 + b_row) * 64
                                          + (ks * 2 + b_u) * 16);
                off = SWZ64(off);
                ldm_x2(bh[nt], bBhi + off);
                ldm_x2(bl[nt], bBlo + off);
            }
#pragma unroll
            for (int mt = 0; mt < 4; mt++)
#pragma unroll
                for (int nt = 0; nt < 4; nt++) {
                    mma16816(acc[mt][nt], ah[mt], bh[nt]);
                    mma16816(acc[mt][nt], ah[mt], bl[nt]);
                    mma16816(acc[mt][nt], al[mt], bh[nt]);
                }
        }
        __syncthreads();
    }

    // epilogue: c-frag thread mapping: rows lr, lr+8; cols lc, lc+1
    const int lr = lane >> 2, lc = (lane & 3) * 2;
#pragma unroll
    for (int mt = 0; mt < 4; mt++) {
#pragma unroll
        for (int nt = 0; nt < 4; nt++) {
            const int m = m0 + wm * 64 + mt * 16 + lr;
            const int n = n0 + wn * 32 + nt * 8 + lc;
            float c0 = acc[mt][nt][0], c1 = acc[mt][nt][1];
            float c2 = acc[mt][nt][2], c3 = acc[mt][nt][3];
            if (MODE == 1) {
                float2 bs = *(const float2*)(bias + n);
                const int h = n >> 6, d = n & 63;
#pragma unroll
                for (int half = 0; half < 2; half++) {
                    const int mr = m + half * 8;
                    const int s = mr >> 1, b = mr & 1;   // BB == 2
                    float2 ov = { (half ? c2 : c0) + bs.x,
                                  (half ? c3 : c1) + bs.y };
                    *(float2*)(out + (((size_t)(b * HH + h)) * SQ + s) * DD + d) = ov;
                }
            } else {
                *(float2*)(out + (size_t)m * EE + n)       = make_float2(c0, c1);
                *(float2*)(out + (size_t)(m + 8) * EE + n) = make_float2(c2, c3);
            }
        }
    }
}

// ---------------- RoPE (in-place on g_Q, g_K) -------------------------------
__global__ __launch_bounds__(256)
void rope_kernel(const float* __restrict__ cosT, const float* __restrict__ sinT)
{
    int gid = blockIdx.x * 256 + threadIdx.x;   // BB*HH*SQ*32 threads
    int d   = gid & 31;
    int row = gid >> 5;                          // bh*SQ + s
    int s   = row & (SQ - 1);
    size_t base = (size_t)row * DD;
    float c1 = cosT[s*DD + d],      s1 = sinT[s*DD + d];
    float c2 = cosT[s*DD + d + 32], s2 = sinT[s*DD + d + 32];

    float q1 = g_Q[base + d], q2 = g_Q[base + d + 32];
    g_Q[base + d]      = q1*c1 - q2*s1;
    g_Q[base + d + 32] = q2*c2 + q1*s2;

    float k1 = g_K[base + d], k2 = g_K[base + d + 32];
    g_K[base + d]      = k1*c1 - k2*s1;
    g_K[base + d + 32] = k2*c2 + k1*s2;
}

// ---------------- Flash attention (causal), fp32 ----------------------------
#define AT_PAD 68
#define AT_SMEM (3 * 64 * AT_PAD * 4)   // 52224 bytes

__global__ __launch_bounds__(256)
void attn_kernel()
{
    extern __shared__ float sm[];
    float* Qs = sm;                      // [64][AT_PAD], pre-scaled Q
    float* KP = sm + 64*AT_PAD;          // [64][AT_PAD], K tile then P tile
    float* Vs = sm + 2*64*AT_PAD;        // [64][AT_PAD]

    const int tid = threadIdx.x;
    const int tx  = tid & 15, ty = tid >> 4;
    const int bh  = blockIdx.y;                       // b*HH + h
    const int qi  = gridDim.x - 1 - blockIdx.x;       // heavy tiles first
    const int s0  = qi * 64;

    const float* Qg = g_Q + ((size_t)bh*SQ + s0) * DD;
    const float* Kg = g_K + (size_t)bh*SQ*DD;
    const float* Vg = g_V + (size_t)bh*SQ*DD;

    // load + pre-scale Q tile
#pragma unroll
    for (int l = 0; l < 4; l++) {
        int v = tid + 256*l;
        int r = v >> 4, seg = (v & 15) * 4;
        float4 q = *(const float4*)(Qg + (size_t)r*DD + seg);
        float4 qs = {q.x*SCALE, q.y*SCALE, q.z*SCALE, q.w*SCALE};
        *(float4*)&Qs[r*AT_PAD + seg] = qs;
    }

    float m_i[4], l_i[4], o[4][4];
#pragma unroll
    for (int i = 0; i < 4; i++) {
        m_i[i] = -1e30f; l_i[i] = 0.f;
#pragma unroll
        for (int j = 0; j < 4; j++) o[i][j] = 0.f;
    }

    for (int jt = 0; jt <= qi; jt++) {
        const int t0 = jt * 64;
        __syncthreads();   // prev P·V done (and Q load on first iter)
#pragma unroll
        for (int l = 0; l < 4; l++) {
            int v = tid + 256*l;
            int r = v >> 4, seg = (v & 15) * 4;
            *(float4*)&KP[r*AT_PAD + seg] = *(const float4*)(Kg + (size_t)(t0 + r)*DD + seg);
            *(float4*)&Vs[r*AT_PAD + seg] = *(const float4*)(Vg + (size_t)(t0 + r)*DD + seg);
        }
        __syncthreads();

        // scores: sc[i][j] = (SCALE*q_row_i) . k_row_j
        float sc[4][4];
#pragma unroll
        for (int i = 0; i < 4; i++)
#pragma unroll
            for (int j = 0; j < 4; j++) sc[i][j] = 0.f;

#pragma unroll
        for (int d4 = 0; d4 < DD; d4 += 4) {
            float4 kv[4];
#pragma unroll
            for (int j = 0; j < 4; j++)
                kv[j] = *(const float4*)&KP[(4*tx + j)*AT_PAD + d4];
#pragma unroll
            for (int i = 0; i < 4; i++) {
                float4 qv = *(const float4*)&Qs[(4*ty + i)*AT_PAD + d4];
#pragma unroll
                for (int j = 0; j < 4; j++)
                    sc[i][j] += qv.x*kv[j].x + qv.y*kv[j].y + qv.z*kv[j].z + qv.w*kv[j].w;
            }
        }

        if (jt == qi) {   // diagonal tile: causal mask
#pragma unroll
            for (int i = 0; i < 4; i++) {
                int r = s0 + 4*ty + i;
#pragma unroll
                for (int j = 0; j < 4; j++) {
                    int t = t0 + 4*tx + j;
                    if (t > r) sc[i][j] = -1e30f;
                }
            }
        }

        // online softmax
        float p[4][4];
#pragma unroll
        for (int i = 0; i < 4; i++) {
            float mx = fmaxf(fmaxf(sc[i][0], sc[i][1]), fmaxf(sc[i][2], sc[i][3]));
#pragma unroll
            for (int w = 1; w < 16; w <<= 1)
                mx = fmaxf(mx, __shfl_xor_sync(0xffffffffu, mx, w));
            float mnew = fmaxf(m_i[i], mx);
            float corr = __expf(m_i[i] - mnew);
            float ps = 0.f;
#pragma unroll
            for (int j = 0; j < 4; j++) { p[i][j] = __expf(sc[i][j] - mnew); ps += p[i][j]; }
#pragma unroll
            for (int w = 1; w < 16; w <<= 1)
                ps += __shfl_xor_sync(0xffffffffu, ps, w);
            l_i[i] = l_i[i]*corr + ps;
            m_i[i] = mnew;
#pragma unroll
            for (int j = 0; j < 4; j++) o[i][j] *= corr;
        }

        __syncthreads();   // all K reads done before overwriting with P
#pragma unroll
        for (int i = 0; i < 4; i++) {
            float4 pv = {p[i][0], p[i][1], p[i][2], p[i][3]};
            *(float4*)&KP[(4*ty + i)*AT_PAD + 4*tx] = pv;
        }
        __syncthreads();

        // O += P * V
#pragma unroll
        for (int t4 = 0; t4 < 64; t4 += 4) {
            float4 vr[4];
#pragma unroll
            for (int tt = 0; tt < 4; tt++)
                vr[tt] = *(const float4*)&Vs[(t4 + tt)*AT_PAD + 4*tx];
#pragma unroll
            for (int i = 0; i < 4; i++) {
                float4 pv = *(const float4*)&KP[(4*ty + i)*AT_PAD + t4];
                o[i][0] += pv.x*vr[0].x + pv.y*vr[1].x + pv.z*vr[2].x + pv.w*vr[3].x;
                o[i][1] += pv.x*vr[0].y + pv.y*vr[1].y + pv.z*vr[2].y + pv.w*vr[3].y;
                o[i][2] += pv.x*vr[0].z + pv.y*vr[1].z + pv.z*vr[2].z + pv.w*vr[3].z;
                o[i][3] += pv.x*vr[0].w + pv.y*vr[1].w + pv.z*vr[2].w + pv.w*vr[3].w;
            }
        }
    }

    // normalize + write to [s][b][e]
    const int b = bh >> 4, h = bh & 15;
#pragma unroll
    for (int i = 0; i < 4; i++) {
        int s = s0 + 4*ty + i;
        float inv = 1.f / l_i[i];
        float4 ov = {o[i][0]*inv, o[i][1]*inv, o[i][2]*inv, o[i][3]*inv};
        *(float4*)&g_A[((size_t)s*BB + b)*EE + h*DD + 4*tx] = ov;
    }
}

// ---------------- RMSNorm (in-place on g_A) ---------------------------------
__global__ __launch_bounds__(256)
void rmsnorm_kernel(const float* __restrict__ w)
{
    const int r = blockIdx.x;
    float* a = g_A + (size_t)r * EE;
    const int tid = threadIdx.x;
    float v[4];
    float ss = 0.f;
#pragma unroll
    for (int l = 0; l < 4; l++) { v[l] = a[tid + 256*l]; ss += v[l]*v[l]; }
#pragma unroll
    for (int ofs = 16; ofs; ofs >>= 1) ss += __shfl_xor_sync(0xffffffffu, ss, ofs);
    __shared__ float red[8];
    if ((tid & 31) == 0) red[tid >> 5] = ss;
    __syncthreads();
    float tot = 0.f;
#pragma unroll
    for (int i = 0; i < 8; i++) tot += red[i];
    float rstd = rsqrtf(tot * (1.f / EE) + RMS_EPS);
#pragma unroll
    for (int l = 0; l < 4; l++) {
        int e = tid + 256*l;
        a[e] = v[l] * rstd * w[e];
    }
}

// ---------------- launch -----------------------------------------------------
extern "C" void kernel_launch(void* const* d_in, const int* in_sizes, int n_in,
                              void* d_out, int out_size)
{
    const float* x    = (const float*)d_in[0];
    // d_in[1] = attn_mask (pure causal, implemented analytically)
    const float* cosT = (const float*)d_in[2];
    const float* sinT = (const float*)d_in[3];
    const float* Wq   = (const float*)d_in[4];
    const float* bq   = (const float*)d_in[5];
    const float* Wk   = (const float*)d_in[6];
    const float* bk   = (const float*)d_in[7];
    const float* Wv   = (const float*)d_in[8];
    const float* bv   = (const float*)d_in[9];
    const float* Wo   = (const float*)d_in[10];
    const float* nw   = (const float*)d_in[11];

    float *pQ, *pK, *pV, *pA;
    __nv_bfloat16 *pxh, *pxl, *pwh, *pwl;
    cudaGetSymbolAddress((void**)&pQ, g_Q);
    cudaGetSymbolAddress((void**)&pK, g_K);
    cudaGetSymbolAddress((void**)&pV, g_V);
    cudaGetSymbolAddress((void**)&pA, g_A);
    cudaGetSymbolAddress((void**)&pxh, g_xhi);
    cudaGetSymbolAddress((void**)&pxl, g_xlo);
    cudaGetSymbolAddress((void**)&pwh, g_whi);
    cudaGetSymbolAddress((void**)&pwl, g_wlo);

    cudaFuncSetAttribute(gemm_mma<0>, cudaFuncAttributeMaxDynamicSharedMemorySize, G_SMEM);
    cudaFuncSetAttribute(gemm_mma<1>, cudaFuncAttributeMaxDynamicSharedMemorySize, G_SMEM);
    cudaFuncSetAttribute(attn_kernel, cudaFuncAttributeMaxDynamicSharedMemorySize, AT_SMEM);

    const int n4x = MM * EE / 4;   // 1,048,576
    const int n4w = EE * EE / 4;   // 262,144
    dim3 ggrid(EE/128, MM/128);    // (8, 32)

    cvt_hilo<<<n4x/256, 256>>>(x, pxh, pxl, n4x);

    cvt_hilo<<<n4w/256, 256>>>(Wq, pwh, pwl, n4w);
    gemm_mma<1><<<ggrid, 256, G_SMEM>>>(pxh, pxl, pwh, pwl, bq, pQ);
    cvt_hilo<<<n4w/256, 256>>>(Wk, pwh, pwl, n4w);
    gemm_mma<1><<<ggrid, 256, G_SMEM>>>(pxh, pxl, pwh, pwl, bk, pK);
    cvt_hilo<<<n4w/256, 256>>>(Wv, pwh, pwl, n4w);
    gemm_mma<1><<<ggrid, 256, G_SMEM>>>(pxh, pxl, pwh, pwl, bv, pV);

    rope_kernel<<<(BB*HH*SQ*32)/256, 256>>>(cosT, sinT);

    attn_kernel<<<dim3(SQ/64, BB*HH), 256, AT_SMEM>>>();

    rmsnorm_kernel<<<MM, 256>>>(nw);

    // reuse x hi/lo buffers for normalized attention output
    cvt_hilo<<<n4x/256, 256>>>(pA, pxh, pxl, n4x);
    cvt_hilo<<<n4w/256, 256>>>(Wo, pwh, pwl, n4w);
    gemm_mma<0><<<ggrid, 256, G_SMEM>>>(pxh, pxl, pwh, pwl, nullptr, (float*)d_out);
}

// round 11
// speedup vs baseline: 3.7241x; 2.4739x over previous
#include <cuda_runtime.h>
#include <cuda_bf16.h>
#include <cstdint>

#define SQ 2048
#define BB 2
#define EE 1024
#define HH 16
#define DD 64
#define MM (SQ*BB)              // 4096 rows (s,b)
#define SCALE 0.125f            // 64^-0.5
#define RMS_EPS 1e-6f

// ---------------- scratch (device globals: no runtime allocation) ----------
__device__ float g_Q[(size_t)BB*HH*SQ*DD];   // [b][h][s][d] fp32 (pre-RoPE)
__device__ float g_K[(size_t)BB*HH*SQ*DD];
__device__ float g_A[(size_t)MM*EE];         // attention out, [s][b][e]
__device__ __nv_bfloat16 g_xhi[(size_t)MM*EE];
__device__ __nv_bfloat16 g_xlo[(size_t)MM*EE];
__device__ __nv_bfloat16 g_whi[(size_t)EE*EE];
__device__ __nv_bfloat16 g_wlo[(size_t)EE*EE];
// bf16 hi/lo Q,K,V in [b][h][s][d] for mma attention (Q pre-scaled)
__device__ __nv_bfloat16 g_Qhi[(size_t)BB*HH*SQ*DD];
__device__ __nv_bfloat16 g_Qlo[(size_t)BB*HH*SQ*DD];
__device__ __nv_bfloat16 g_Khi[(size_t)BB*HH*SQ*DD];
__device__ __nv_bfloat16 g_Klo[(size_t)BB*HH*SQ*DD];
__device__ __nv_bfloat16 g_Vhi[(size_t)BB*HH*SQ*DD];
__device__ __nv_bfloat16 g_Vlo[(size_t)BB*HH*SQ*DD];

// ---------------- PTX helpers (plain sm_103-safe: no 'a' features) ----------
__device__ __forceinline__ uint32_t smem_u32(const void* p) {
    uint32_t a;
    asm("{ .reg .u64 t; cvta.to.shared.u64 t, %1; cvt.u32.u64 %0, t; }"
        : "=r"(a) : "l"(p));
    return a;
}

__device__ __forceinline__ void cp_async16(uint32_t smem, const void* g) {
    asm volatile("cp.async.cg.shared.global [%0], [%1], 16;"
                 :: "r"(smem), "l"(g) : "memory");
}
#define CP_COMMIT() asm volatile("cp.async.commit_group;" ::: "memory")
#define CP_WAIT(n)  asm volatile("cp.async.wait_group %0;" :: "n"(n) : "memory")

__device__ __forceinline__ void ldm_x4(uint32_t* r, uint32_t addr) {
    asm volatile("ldmatrix.sync.aligned.m8n8.x4.shared.b16 {%0,%1,%2,%3}, [%4];"
                 : "=r"(r[0]), "=r"(r[1]), "=r"(r[2]), "=r"(r[3]) : "r"(addr));
}
__device__ __forceinline__ void ldm_x2(uint32_t* r, uint32_t addr) {
    asm volatile("ldmatrix.sync.aligned.m8n8.x2.shared.b16 {%0,%1}, [%2];"
                 : "=r"(r[0]), "=r"(r[1]) : "r"(addr));
}
__device__ __forceinline__ void ldm_x2t(uint32_t* r, uint32_t addr) {
    asm volatile("ldmatrix.sync.aligned.m8n8.x2.trans.shared.b16 {%0,%1}, [%2];"
                 : "=r"(r[0]), "=r"(r[1]) : "r"(addr));
}

__device__ __forceinline__ void mma16816(float* c, const uint32_t* a, const uint32_t* b) {
    asm volatile(
        "mma.sync.aligned.m16n8k16.row.col.f32.bf16.bf16.f32 "
        "{%0,%1,%2,%3}, {%4,%5,%6,%7}, {%8,%9}, {%0,%1,%2,%3};"
        : "+f"(c[0]), "+f"(c[1]), "+f"(c[2]), "+f"(c[3])
        : "r"(a[0]), "r"(a[1]), "r"(a[2]), "r"(a[3]), "r"(b[0]), "r"(b[1]));
}

// low half <- lo, high half <- hi (cvt.bf16x2.f32 d,a,b: d.hi=cvt(a), d.lo=cvt(b))
__device__ __forceinline__ uint32_t pack_bf16x2(float lo, float hi) {
    uint32_t r;
    asm("cvt.rn.bf16x2.f32 %0, %1, %2;" : "=r"(r) : "f"(hi), "f"(lo));
    return r;
}

#define SWZ64(off)  ((off) ^ (((off) >> 3) & 0x30))
#define SWZ128(off) ((off) ^ (((off) >> 3) & 0x70))

// ---------------- fp32 -> (hi, lo) bf16 split -------------------------------
__global__ __launch_bounds__(256)
void cvt_hilo(const float* __restrict__ x, __nv_bfloat16* __restrict__ hi,
              __nv_bfloat16* __restrict__ lo, int n4)
{
    int i = blockIdx.x * 256 + threadIdx.x;
    if (i >= n4) return;
    float4 v = ((const float4*)x)[i];
    float vv[4] = {v.x, v.y, v.z, v.w};
    __nv_bfloat16 h[4], l[4];
#pragma unroll
    for (int j = 0; j < 4; j++) {
        h[j] = __float2bfloat16(vv[j]);
        l[j] = __float2bfloat16(vv[j] - __bfloat162float(h[j]));
    }
    __nv_bfloat162 h01, h23, l01, l23;
    h01.x = h[0]; h01.y = h[1]; h23.x = h[2]; h23.y = h[3];
    l01.x = l[0]; l01.y = l[1]; l23.x = l[2]; l23.y = l[3];
    uint2 uh, ul;
    uh.x = *(uint32_t*)&h01; uh.y = *(uint32_t*)&h23;
    ul.x = *(uint32_t*)&l01; ul.y = *(uint32_t*)&l23;
    ((uint2*)hi)[i] = uh;
    ((uint2*)lo)[i] = ul;
}

// ---------------- mma.sync GEMM: C = A * W^T (+bias) ------------------------
// MODE 0: C[m][n] row-major fp32 (no bias).
// MODE 1: fp32 scatter to BHSD with bias.
// MODE 2: bf16 hi/lo scatter to BHSD with bias (for V).
#define G_STAGE 32768                   // 4 matrices x 128 rows x 64B
#define G_SMEM  (2 * G_STAGE)

template<int MODE>
__global__ __launch_bounds__(256, 1)
void gemm_mma(const __nv_bfloat16* __restrict__ Ahi, const __nv_bfloat16* __restrict__ Alo,
              const __nv_bfloat16* __restrict__ Bhi, const __nv_bfloat16* __restrict__ Blo,
              const float* __restrict__ bias, float* __restrict__ out,
              __nv_bfloat16* __restrict__ ohi, __nv_bfloat16* __restrict__ olo)
{
    extern __shared__ char dsm[];
    const uint32_t sb = smem_u32(dsm);
    const int tid  = threadIdx.x;
    const int wid  = tid >> 5, lane = tid & 31;
    const int wm   = wid >> 2, wn = wid & 3;      // warp grid 2x4
    const int m0   = blockIdx.y * 128;
    const int n0   = blockIdx.x * 128;

    float acc[4][4][4];
#pragma unroll
    for (int i = 0; i < 4; i++)
#pragma unroll
        for (int j = 0; j < 4; j++)
#pragma unroll
            for (int k = 0; k < 4; k++) acc[i][j][k] = 0.f;

    const int a_row = (lane & 15);
    const int a_u   = (lane >> 4);
    const int b_row = (lane & 7);
    const int b_u   = ((lane & 15) >> 3);

    auto issue = [&](int ck, int st) {
        const uint32_t base = sb + st * G_STAGE;
#pragma unroll
        for (int i = 0; i < 8; i++) {
            const int t   = i >> 1;
            const int cid = (i & 1) * 256 + tid;
            const int row = cid >> 2, u = cid & 3;
            const __nv_bfloat16* src = (t == 0) ? Ahi : (t == 1) ? Alo
                                     : (t == 2) ? Bhi : Blo;
            const int r0 = (t < 2) ? m0 : n0;
            const char* g = (const char*)(src + (size_t)(r0 + row) * EE + ck * 32) + u * 16;
            uint32_t off = (uint32_t)(row * 64 + u * 16);
            cp_async16(base + t * 8192 + SWZ64(off), g);
        }
    };

    issue(0, 0); CP_COMMIT();

    for (int ck = 0; ck < 32; ck++) {
        const int st = ck & 1;
        if (ck < 31) { issue(ck + 1, st ^ 1); CP_COMMIT(); CP_WAIT(1); }
        else         { CP_WAIT(0); }
        __syncthreads();

        const uint32_t bAhi = sb + st * G_STAGE;
        const uint32_t bAlo = bAhi + 8192;
        const uint32_t bBhi = bAhi + 16384;
        const uint32_t bBlo = bAhi + 24576;

#pragma unroll
        for (int ks = 0; ks < 2; ks++) {
            uint32_t ah[4][4], al[4][4], bh[4][2], bl[4][2];
#pragma unroll
            for (int mt = 0; mt < 4; mt++) {
                uint32_t off = (uint32_t)((wm * 64 + mt * 16 + a_row) * 64
                                          + (ks * 2 + a_u) * 16);
                off = SWZ64(off);
                ldm_x4(ah[mt], bAhi + off);
                ldm_x4(al[mt], bAlo + off);
            }
#pragma unroll
            for (int nt = 0; nt < 4; nt++) {
                uint32_t off = (uint32_t)((wn * 32 + nt * 8 + b_row) * 64
                                          + (ks * 2 + b_u) * 16);
                off = SWZ64(off);
                ldm_x2(bh[nt], bBhi + off);
                ldm_x2(bl[nt], bBlo + off);
            }
#pragma unroll
            for (int mt = 0; mt < 4; mt++)
#pragma unroll
                for (int nt = 0; nt < 4; nt++) {
                    mma16816(acc[mt][nt], ah[mt], bh[nt]);
                    mma16816(acc[mt][nt], ah[mt], bl[nt]);
                    mma16816(acc[mt][nt], al[mt], bh[nt]);
                }
        }
        __syncthreads();
    }

    const int lr = lane >> 2, lc = (lane & 3) * 2;
#pragma unroll
    for (int mt = 0; mt < 4; mt++) {
#pragma unroll
        for (int nt = 0; nt < 4; nt++) {
            const int m = m0 + wm * 64 + mt * 16 + lr;
            const int n = n0 + wn * 32 + nt * 8 + lc;
            float c0 = acc[mt][nt][0], c1 = acc[mt][nt][1];
            float c2 = acc[mt][nt][2], c3 = acc[mt][nt][3];
            if (MODE == 0) {
                *(float2*)(out + (size_t)m * EE + n)       = make_float2(c0, c1);
                *(float2*)(out + (size_t)(m + 8) * EE + n) = make_float2(c2, c3);
            } else {
                float2 bs = *(const float2*)(bias + n);
                const int h = n >> 6, d = n & 63;
#pragma unroll
                for (int half = 0; half < 2; half++) {
                    const int mr = m + half * 8;
                    const int s = mr >> 1, b = mr & 1;   // BB == 2
                    const size_t idx = (((size_t)(b * HH + h)) * SQ + s) * DD + d;
                    float va = (half ? c2 : c0) + bs.x;
                    float vb = (half ? c3 : c1) + bs.y;
                    if (MODE == 1) {
                        *(float2*)(out + idx) = make_float2(va, vb);
                    } else {   // MODE 2: bf16 hi/lo
                        __nv_bfloat16 ha = __float2bfloat16(va);
                        __nv_bfloat16 hb = __float2bfloat16(vb);
                        float la = va - __bfloat162float(ha);
                        float lb = vb - __bfloat162float(hb);
                        uint32_t hp = ((uint32_t)*(uint16_t*)&hb << 16) | *(uint16_t*)&ha;
                        *(uint32_t*)(ohi + idx) = hp;
                        *(uint32_t*)(olo + idx) = pack_bf16x2(la, lb);
                    }
                }
            }
        }
    }
}

// ---------------- RoPE + bf16 hi/lo convert (Q scaled) ----------------------
__global__ __launch_bounds__(256)
void rope_cvt(const float* __restrict__ cosT, const float* __restrict__ sinT)
{
    int gid = blockIdx.x * 256 + threadIdx.x;   // BB*HH*SQ*32 threads
    int d   = gid & 31;
    int row = gid >> 5;                          // bh*SQ + s
    int s   = row & (SQ - 1);
    size_t base = (size_t)row * DD;
    float c1 = cosT[s*DD + d],      s1 = sinT[s*DD + d];
    float c2 = cosT[s*DD + d + 32], s2 = sinT[s*DD + d + 32];

    float q1 = g_Q[base + d], q2 = g_Q[base + d + 32];
    float k1 = g_K[base + d], k2 = g_K[base + d + 32];
    float qa = (q1*c1 - q2*s1) * SCALE;
    float qb = (q2*c2 + q1*s2) * SCALE;
    float ka = k1*c1 - k2*s1;
    float kb = k2*c2 + k1*s2;

    __nv_bfloat16 h;
    h = __float2bfloat16(qa); g_Qhi[base+d] = h;
    g_Qlo[base+d] = __float2bfloat16(qa - __bfloat162float(h));
    h = __float2bfloat16(qb); g_Qhi[base+d+32] = h;
    g_Qlo[base+d+32] = __float2bfloat16(qb - __bfloat162float(h));
    h = __float2bfloat16(ka); g_Khi[base+d] = h;
    g_Klo[base+d] = __float2bfloat16(ka - __bfloat162float(h));
    h = __float2bfloat16(kb); g_Khi[base+d+32] = h;
    g_Klo[base+d+32] = __float2bfloat16(kb - __bfloat162float(h));
}

// ---------------- Flash attention on mma.sync (causal) ----------------------
// CTA: 128 q-rows, 8 warps (one m16 band each). K/V tiles 64 wide, cp.async
// double-buffered. 3-term hi/lo split on both Q.K^T and P.V; P stays in regs.
#define ATT_SMEM 65536   // 2 stages x 32KB (Khi,Klo,Vhi,Vlo @ 8KB each)

__global__ __launch_bounds__(256, 1)
void attn_mma()
{
    extern __shared__ char dsm[];
    const uint32_t sb = smem_u32(dsm);
    const int tid = threadIdx.x, wid = tid >> 5, lane = tid & 31;
    const int bh  = blockIdx.y;                       // b*HH + h
    const int qi  = gridDim.x - 1 - (int)blockIdx.x;  // heavy tiles first
    const int s0  = qi * 128;
    const int njt = 2 * qi + 2;
    const int lr  = lane >> 2, lc = (lane & 3) * 2;

    const size_t headoff = (size_t)bh * SQ * DD;

    // ---- stage Q (hi at sb, lo at sb+16384; 16KB each), then to registers
#pragma unroll
    for (int i = 0; i < 4; i++) {
        int cid = tid + 256 * i;                 // 0..1023
        int row = cid >> 3, seg = cid & 7;
        uint32_t off = SWZ128((uint32_t)(row * 128 + seg * 16));
        const size_t g = headoff + (size_t)(s0 + row) * DD + seg * 8;
        cp_async16(sb + off,         g_Qhi + g);
        cp_async16(sb + 16384 + off, g_Qlo + g);
    }
    CP_COMMIT(); CP_WAIT(0); __syncthreads();

    uint32_t qh[4][4], ql[4][4];
    {
        const int arow = lane & 15, au = lane >> 4;
#pragma unroll
        for (int kc = 0; kc < 4; kc++) {
            uint32_t off = SWZ128((uint32_t)((wid * 16 + arow) * 128 + kc * 32 + au * 16));
            ldm_x4(qh[kc], sb + off);
            ldm_x4(ql[kc], sb + 16384 + off);
        }
    }
    __syncthreads();   // done reading Q smem before K/V overwrite

    auto issueKV = [&](int jt, int st) {
        const uint32_t base = sb + st * 32768;
        const size_t gofs = headoff + (size_t)(jt * 64) * DD;
#pragma unroll
        for (int i = 0; i < 2; i++) {
            int cid = tid + 256 * i;             // 0..511
            int row = cid >> 3, seg = cid & 7;
            uint32_t off = SWZ128((uint32_t)(row * 128 + seg * 16));
            const size_t g = gofs + (size_t)row * DD + seg * 8;
            cp_async16(base +         off, g_Khi + g);
            cp_async16(base + 8192  + off, g_Klo + g);
            cp_async16(base + 16384 + off, g_Vhi + g);
            cp_async16(base + 24576 + off, g_Vlo + g);
        }
    };

    float m_[2] = {-1e30f, -1e30f}, l_[2] = {0.f, 0.f};
    float o[8][4];
#pragma unroll
    for (int nt = 0; nt < 8; nt++)
#pragma unroll
        for (int k = 0; k < 4; k++) o[nt][k] = 0.f;

    issueKV(0, 0); CP_COMMIT();

    for (int jt = 0; jt < njt; jt++) {
        const int st = jt & 1;
        if (jt + 1 < njt) { issueKV(jt + 1, st ^ 1); CP_COMMIT(); CP_WAIT(1); }
        else              { CP_WAIT(0); }
        __syncthreads();

        const uint32_t bK = sb + st * 32768;

        // ---- scores = Q . K^T (3-term)
        float sc[8][4];
#pragma unroll
        for (int nt = 0; nt < 8; nt++)
#pragma unroll
            for (int k = 0; k < 4; k++) sc[nt][k] = 0.f;
        {
            const int brow = lane & 7, bu = (lane >> 3) & 1;
#pragma unroll
            for (int kc = 0; kc < 4; kc++) {
                uint32_t kbh[8][2], kbl[8][2];
#pragma unroll
                for (int nt = 0; nt < 8; nt++) {
                    uint32_t off = SWZ128((uint32_t)((nt * 8 + brow) * 128 + kc * 32 + bu * 16));
                    ldm_x2(kbh[nt], bK + off);
                    ldm_x2(kbl[nt], bK + 8192 + off);
                }
#pragma unroll
                for (int nt = 0; nt < 8; nt++) {
                    mma16816(sc[nt], qh[kc], kbh[nt]);
                    mma16816(sc[nt], qh[kc], kbl[nt]);
                    mma16816(sc[nt], ql[kc], kbh[nt]);
                }
            }
        }

        // ---- causal mask (only boundary tiles)
        if (jt >= 2 * qi) {
            const int t0 = jt * 64;
            const int r0 = s0 + wid * 16 + lr;
#pragma unroll
            for (int nt = 0; nt < 8; nt++) {
                int t = t0 + nt * 8 + lc;
                if (t     > r0)     sc[nt][0] = -1e30f;
                if (t + 1 > r0)     sc[nt][1] = -1e30f;
                if (t     > r0 + 8) sc[nt][2] = -1e30f;
                if (t + 1 > r0 + 8) sc[nt][3] = -1e30f;
            }
        }

        // ---- online softmax (rows lr and lr+8)
        float mx0 = -1e30f, mx1 = -1e30f;
#pragma unroll
        for (int nt = 0; nt < 8; nt++) {
            mx0 = fmaxf(mx0, fmaxf(sc[nt][0], sc[nt][1]));
            mx1 = fmaxf(mx1, fmaxf(sc[nt][2], sc[nt][3]));
        }
        mx0 = fmaxf(mx0, __shfl_xor_sync(0xffffffffu, mx0, 1));
        mx0 = fmaxf(mx0, __shfl_xor_sync(0xffffffffu, mx0, 2));
        mx1 = fmaxf(mx1, __shfl_xor_sync(0xffffffffu, mx1, 1));
        mx1 = fmaxf(mx1, __shfl_xor_sync(0xffffffffu, mx1, 2));
        float mn0 = fmaxf(m_[0], mx0), mn1 = fmaxf(m_[1], mx1);
        float corr0 = __expf(m_[0] - mn0), corr1 = __expf(m_[1] - mn1);
        m_[0] = mn0; m_[1] = mn1;
        float su0 = 0.f, su1 = 0.f;
#pragma unroll
        for (int nt = 0; nt < 8; nt++) {
            sc[nt][0] = __expf(sc[nt][0] - mn0);
            sc[nt][1] = __expf(sc[nt][1] - mn0);
            sc[nt][2] = __expf(sc[nt][2] - mn1);
            sc[nt][3] = __expf(sc[nt][3] - mn1);
            su0 += sc[nt][0] + sc[nt][1];
            su1 += sc[nt][2] + sc[nt][3];
        }
        su0 += __shfl_xor_sync(0xffffffffu, su0, 1);
        su0 += __shfl_xor_sync(0xffffffffu, su0, 2);
        su1 += __shfl_xor_sync(0xffffffffu, su1, 1);
        su1 += __shfl_xor_sync(0xffffffffu, su1, 2);
        l_[0] = l_[0] * corr0 + su0;
        l_[1] = l_[1] * corr1 + su1;
#pragma unroll
        for (int nt = 0; nt < 8; nt++) {
            o[nt][0] *= corr0; o[nt][1] *= corr0;
            o[nt][2] *= corr1; o[nt][3] *= corr1;
        }

        // ---- P -> bf16 hi/lo A-fragments (exact truncation split, in regs)
        uint32_t pah[4][4], pal[4][4];
#pragma unroll
        for (int c = 0; c < 4; c++) {
#pragma unroll
            for (int q = 0; q < 4; q++) {
                const int nt = 2 * c + (q >> 1);          // tile pair
                const int e0 = (q & 1) * 2;               // c0/c1 or c2/c3
                float a = sc[nt][e0], b = sc[nt][e0 + 1];
                uint32_t ua = __float_as_uint(a), ub = __float_as_uint(b);
                pah[c][(q & 1) | ((q >> 1) << 1)] = 0;     // placeholder (overwritten)
                uint32_t hp = __byte_perm(ua, ub, 0x7632); // {a.hi16, b.hi16}
                float la = a - __uint_as_float(ua & 0xFFFF0000u);
                float lb = b - __uint_as_float(ub & 0xFFFF0000u);
                // frag reg index: a0=(r,c) a1=(r+8,c) a2=(r,c+8) a3=(r+8,c+8)
                const int ri = (q & 1) + ((q >> 1) << 1);  // 0:a0 1:a1 2:a2 3:a3
                pah[c][ri] = hp;
                pal[c][ri] = pack_bf16x2(la, lb);
            }
        }

        // ---- O += P . V (3-term), V via ldmatrix.trans
        const uint32_t bV = bK + 16384;
        {
            const int vrow = lane & 15;
#pragma unroll
            for (int tc = 0; tc < 4; tc++) {
                uint32_t vbh[8][2], vbl[8][2];
#pragma unroll
                for (int nt = 0; nt < 8; nt++) {
                    uint32_t off = SWZ128((uint32_t)((tc * 16 + vrow) * 128 + nt * 16));
                    ldm_x2t(vbh[nt], bV + off);
                    ldm_x2t(vbl[nt], bV + 8192 + off);
                }
#pragma unroll
                for (int nt = 0; nt < 8; nt++) {
                    mma16816(o[nt], pah[tc], vbh[nt]);
                    mma16816(o[nt], pah[tc], vbl[nt]);
                    mma16816(o[nt], pal[tc], vbh[nt]);
                }
            }
        }
        __syncthreads();
    }

    // ---- normalize + write [s][b][e]
    const float inv0 = 1.f / l_[0], inv1 = 1.f / l_[1];
    const int b = bh >> 4, h = bh & 15;
    const int sA = s0 + wid * 16 + lr;
#pragma unroll
    for (int nt = 0; nt < 8; nt++) {
        const int d = nt * 8 + lc;
        *(float2*)&g_A[((size_t)sA * BB + b) * EE + h * DD + d] =
            make_float2(o[nt][0] * inv0, o[nt][1] * inv0);
        *(float2*)&g_A[((size_t)(sA + 8) * BB + b) * EE + h * DD + d] =
            make_float2(o[nt][2] * inv1, o[nt][3] * inv1);
    }
}

// ---------------- RMSNorm (in-place on g_A) ---------------------------------
__global__ __launch_bounds__(256)
void rmsnorm_kernel(const float* __restrict__ w)
{
    const int r = blockIdx.x;
    float* a = g_A + (size_t)r * EE;
    const int tid = threadIdx.x;
    float v[4];
    float ss = 0.f;
#pragma unroll
    for (int l = 0; l < 4; l++) { v[l] = a[tid + 256*l]; ss += v[l]*v[l]; }
#pragma unroll
    for (int ofs = 16; ofs; ofs >>= 1) ss += __shfl_xor_sync(0xffffffffu, ss, ofs);
    __shared__ float red[8];
    if ((tid & 31) == 0) red[tid >> 5] = ss;
    __syncthreads();
    float tot = 0.f;
#pragma unroll
    for (int i = 0; i < 8; i++) tot += red[i];
    float rstd = rsqrtf(tot * (1.f / EE) + RMS_EPS);
#pragma unroll
    for (int l = 0; l < 4; l++) {
        int e = tid + 256*l;
        a[e] = v[l] * rstd * w[e];
    }
}

// ---------------- launch -----------------------------------------------------
extern "C" void kernel_launch(void* const* d_in, const int* in_sizes, int n_in,
                              void* d_out, int out_size)
{
    const float* x    = (const float*)d_in[0];
    // d_in[1] = attn_mask (pure causal, implemented analytically)
    const float* cosT = (const float*)d_in[2];
    const float* sinT = (const float*)d_in[3];
    const float* Wq   = (const float*)d_in[4];
    const float* bq   = (const float*)d_in[5];
    const float* Wk   = (const float*)d_in[6];
    const float* bk   = (const float*)d_in[7];
    const float* Wv   = (const float*)d_in[8];
    const float* bv   = (const float*)d_in[9];
    const float* Wo   = (const float*)d_in[10];
    const float* nw   = (const float*)d_in[11];

    float *pQ, *pK, *pA;
    __nv_bfloat16 *pxh, *pxl, *pwh, *pwl, *pVhi, *pVlo;
    cudaGetSymbolAddress((void**)&pQ, g_Q);
    cudaGetSymbolAddress((void**)&pK, g_K);
    cudaGetSymbolAddress((void**)&pA, g_A);
    cudaGetSymbolAddress((void**)&pxh, g_xhi);
    cudaGetSymbolAddress((void**)&pxl, g_xlo);
    cudaGetSymbolAddress((void**)&pwh, g_whi);
    cudaGetSymbolAddress((void**)&pwl, g_wlo);
    cudaGetSymbolAddress((void**)&pVhi, g_Vhi);
    cudaGetSymbolAddress((void**)&pVlo, g_Vlo);

    cudaFuncSetAttribute(gemm_mma<0>, cudaFuncAttributeMaxDynamicSharedMemorySize, G_SMEM);
    cudaFuncSetAttribute(gemm_mma<1>, cudaFuncAttributeMaxDynamicSharedMemorySize, G_SMEM);
    cudaFuncSetAttribute(gemm_mma<2>, cudaFuncAttributeMaxDynamicSharedMemorySize, G_SMEM);
    cudaFuncSetAttribute(attn_mma,   cudaFuncAttributeMaxDynamicSharedMemorySize, ATT_SMEM);

    const int n4x = MM * EE / 4;   // 1,048,576
    const int n4w = EE * EE / 4;   // 262,144
    dim3 ggrid(EE/128, MM/128);    // (8, 32)

    cvt_hilo<<<n4x/256, 256>>>(x, pxh, pxl, n4x);

    cvt_hilo<<<n4w/256, 256>>>(Wq, pwh, pwl, n4w);
    gemm_mma<1><<<ggrid, 256, G_SMEM>>>(pxh, pxl, pwh, pwl, bq, pQ, nullptr, nullptr);
    cvt_hilo<<<n4w/256, 256>>>(Wk, pwh, pwl, n4w);
    gemm_mma<1><<<ggrid, 256, G_SMEM>>>(pxh, pxl, pwh, pwl, bk, pK, nullptr, nullptr);
    cvt_hilo<<<n4w/256, 256>>>(Wv, pwh, pwl, n4w);
    gemm_mma<2><<<ggrid, 256, G_SMEM>>>(pxh, pxl, pwh, pwl, bv, nullptr, pVhi, pVlo);

    rope_cvt<<<(BB*HH*SQ*32)/256, 256>>>(cosT, sinT);

    attn_mma<<<dim3(SQ/128, BB*HH), 256, ATT_SMEM>>>();

    rmsnorm_kernel<<<MM, 256>>>(nw);

    cvt_hilo<<<n4x/256, 256>>>(pA, pxh, pxl, n4x);
    cvt_hilo<<<n4w/256, 256>>>(Wo, pwh, pwl, n4w);
    gemm_mma<0><<<ggrid, 256, G_SMEM>>>(pxh, pxl, pwh, pwl, nullptr, (float*)d_out, nullptr, nullptr);
}

// round 13
// speedup vs baseline: 4.1178x; 1.1057x over previous
#include <cuda_runtime.h>
#include <cuda_bf16.h>
#include <cstdint>

#define SQ 2048
#define BB 2
#define EE 1024
#define HH 16
#define DD 64
#define MM (SQ*BB)              // 4096 rows (s,b)
#define SCALE 0.125f            // 64^-0.5
#define RMS_EPS 1e-6f

// ---------------- scratch (device globals: no runtime allocation) ----------
__device__ float g_Q[(size_t)BB*HH*SQ*DD];   // [b][h][s][d] fp32 (pre-RoPE)
__device__ float g_K[(size_t)BB*HH*SQ*DD];
__device__ float g_A[(size_t)MM*EE];         // attention out, [s][b][e]
__device__ __nv_bfloat16 g_xhi[(size_t)MM*EE];
__device__ __nv_bfloat16 g_xlo[(size_t)MM*EE];
__device__ __nv_bfloat16 g_wqhi[(size_t)EE*EE], g_wqlo[(size_t)EE*EE];
__device__ __nv_bfloat16 g_wkhi[(size_t)EE*EE], g_wklo[(size_t)EE*EE];
__device__ __nv_bfloat16 g_wvhi[(size_t)EE*EE], g_wvlo[(size_t)EE*EE];
__device__ __nv_bfloat16 g_wohi[(size_t)EE*EE], g_wolo[(size_t)EE*EE];
// bf16 hi/lo Q,K,V in [b][h][s][d] for mma attention (Q pre-scaled)
__device__ __nv_bfloat16 g_Qhi[(size_t)BB*HH*SQ*DD];
__device__ __nv_bfloat16 g_Qlo[(size_t)BB*HH*SQ*DD];
__device__ __nv_bfloat16 g_Khi[(size_t)BB*HH*SQ*DD];
__device__ __nv_bfloat16 g_Klo[(size_t)BB*HH*SQ*DD];
__device__ __nv_bfloat16 g_Vhi[(size_t)BB*HH*SQ*DD];
__device__ __nv_bfloat16 g_Vlo[(size_t)BB*HH*SQ*DD];

// ---------------- PTX helpers (plain sm_103-safe: no 'a' features) ----------
__device__ __forceinline__ uint32_t smem_u32(const void* p) {
    uint32_t a;
    asm("{ .reg .u64 t; cvta.to.shared.u64 t, %1; cvt.u32.u64 %0, t; }"
        : "=r"(a) : "l"(p));
    return a;
}

__device__ __forceinline__ void cp_async16(uint32_t smem, const void* g) {
    asm volatile("cp.async.cg.shared.global [%0], [%1], 16;"
                 :: "r"(smem), "l"(g) : "memory");
}
#define CP_COMMIT() asm volatile("cp.async.commit_group;" ::: "memory")
#define CP_WAIT(n)  asm volatile("cp.async.wait_group %0;" :: "n"(n) : "memory")

__device__ __forceinline__ void ldm_x4(uint32_t* r, uint32_t addr) {
    asm volatile("ldmatrix.sync.aligned.m8n8.x4.shared.b16 {%0,%1,%2,%3}, [%4];"
                 : "=r"(r[0]), "=r"(r[1]), "=r"(r[2]), "=r"(r[3]) : "r"(addr));
}
__device__ __forceinline__ void ldm_x2(uint32_t* r, uint32_t addr) {
    asm volatile("ldmatrix.sync.aligned.m8n8.x2.shared.b16 {%0,%1}, [%2];"
                 : "=r"(r[0]), "=r"(r[1]) : "r"(addr));
}
__device__ __forceinline__ void ldm_x2t(uint32_t* r, uint32_t addr) {
    asm volatile("ldmatrix.sync.aligned.m8n8.x2.trans.shared.b16 {%0,%1}, [%2];"
                 : "=r"(r[0]), "=r"(r[1]) : "r"(addr));
}

__device__ __forceinline__ void mma16816(float* c, const uint32_t* a, const uint32_t* b) {
    asm volatile(
        "mma.sync.aligned.m16n8k16.row.col.f32.bf16.bf16.f32 "
        "{%0,%1,%2,%3}, {%4,%5,%6,%7}, {%8,%9}, {%0,%1,%2,%3};"
        : "+f"(c[0]), "+f"(c[1]), "+f"(c[2]), "+f"(c[3])
        : "r"(a[0]), "r"(a[1]), "r"(a[2]), "r"(a[3]), "r"(b[0]), "r"(b[1]));
}

// low half <- lo, high half <- hi (cvt.bf16x2.f32 d,a,b: d.hi=cvt(a), d.lo=cvt(b))
__device__ __forceinline__ uint32_t pack_bf16x2(float lo, float hi) {
    uint32_t r;
    asm("cvt.rn.bf16x2.f32 %0, %1, %2;" : "=r"(r) : "f"(hi), "f"(lo));
    return r;
}

#define SWZ128(off) ((off) ^ (((off) >> 3) & 0x70))

// ---------------- fp32 -> (hi, lo) bf16 split -------------------------------
__device__ __forceinline__ void split4(float4 v, uint2& uh, uint2& ul) {
    float vv[4] = {v.x, v.y, v.z, v.w};
    __nv_bfloat16 h[4], l[4];
#pragma unroll
    for (int j = 0; j < 4; j++) {
        h[j] = __float2bfloat16(vv[j]);
        l[j] = __float2bfloat16(vv[j] - __bfloat162float(h[j]));
    }
    __nv_bfloat162 h01, h23, l01, l23;
    h01.x = h[0]; h01.y = h[1]; h23.x = h[2]; h23.y = h[3];
    l01.x = l[0]; l01.y = l[1]; l23.x = l[2]; l23.y = l[3];
    uh.x = *(uint32_t*)&h01; uh.y = *(uint32_t*)&h23;
    ul.x = *(uint32_t*)&l01; ul.y = *(uint32_t*)&l23;
}

__global__ __launch_bounds__(256)
void cvt_hilo(const float* __restrict__ x, __nv_bfloat16* __restrict__ hi,
              __nv_bfloat16* __restrict__ lo, int n4)
{
    int i = blockIdx.x * 256 + threadIdx.x;
    if (i >= n4) return;
    uint2 uh, ul;
    split4(((const float4*)x)[i], uh, ul);
    ((uint2*)hi)[i] = uh;
    ((uint2*)lo)[i] = ul;
}

// all 4 weights in one pass
__global__ __launch_bounds__(256)
void cvt_w4(const float* __restrict__ wq, const float* __restrict__ wk,
            const float* __restrict__ wv, const float* __restrict__ wo)
{
    int i = blockIdx.x * 256 + threadIdx.x;    // 0 .. EE*EE/4-1
    uint2 uh, ul;
    split4(((const float4*)wq)[i], uh, ul);
    ((uint2*)g_wqhi)[i] = uh; ((uint2*)g_wqlo)[i] = ul;
    split4(((const float4*)wk)[i], uh, ul);
    ((uint2*)g_wkhi)[i] = uh; ((uint2*)g_wklo)[i] = ul;
    split4(((const float4*)wv)[i], uh, ul);
    ((uint2*)g_wvhi)[i] = uh; ((uint2*)g_wvlo)[i] = ul;
    split4(((const float4*)wo)[i], uh, ul);
    ((uint2*)g_wohi)[i] = uh; ((uint2*)g_wolo)[i] = ul;
}

// ---------------- mma.sync GEMM: C = A * W^T (+bias) ------------------------
// MODE 0: C[m][n] row-major fp32 (no bias).
// MODE 1: fp32 scatter to BHSD with bias.
// MODE 2: bf16 hi/lo scatter to BHSD with bias (for V).
// CTA 128x128, 8 warps (2x4), warp tile 64x32. K-chunk 64 (16 chunks),
// 3-stage cp.async pipeline, SWZ128 smem, B frags via ldmatrix.x4 pairs.
#define G_STAGE 65536                   // 4 matrices x 128 rows x 128B
#define G_SMEM  (3 * G_STAGE)           // 196608

template<int MODE>
__global__ __launch_bounds__(256, 1)
void gemm_mma(const __nv_bfloat16* __restrict__ Ahi, const __nv_bfloat16* __restrict__ Alo,
              const __nv_bfloat16* __restrict__ Bhi, const __nv_bfloat16* __restrict__ Blo,
              const float* __restrict__ bias, float* __restrict__ out,
              __nv_bfloat16* __restrict__ ohi, __nv_bfloat16* __restrict__ olo)
{
    extern __shared__ char dsm[];
    const uint32_t sb = smem_u32(dsm);
    const int tid  = threadIdx.x;
    const int wid  = tid >> 5, lane = tid & 31;
    const int wm   = wid >> 2, wn = wid & 3;      // warp grid 2x4
    const int m0   = blockIdx.y * 128;
    const int n0   = blockIdx.x * 128;

    float acc[4][4][4];
#pragma unroll
    for (int i = 0; i < 4; i++)
#pragma unroll
        for (int j = 0; j < 4; j++)
#pragma unroll
            for (int k = 0; k < 4; k++) acc[i][j][k] = 0.f;

    auto issue = [&](int ck, int st) {
        const uint32_t base = sb + st * G_STAGE;
#pragma unroll
        for (int i = 0; i < 16; i++) {
            const int t   = i >> 2;                   // matrix 0..3
            const int cid = (i & 3) * 256 + tid;      // 0..1023
            const int row = cid >> 3, seg = cid & 7;
            const __nv_bfloat16* src = (t == 0) ? Ahi : (t == 1) ? Alo
                                     : (t == 2) ? Bhi : Blo;
            const int r0 = (t < 2) ? m0 : n0;
            const __nv_bfloat16* g = src + (size_t)(r0 + row) * EE + ck * 64 + seg * 8;
            uint32_t off = SWZ128((uint32_t)(row * 128 + seg * 16));
            cp_async16(base + t * 16384 + off, g);
        }
    };

    issue(0, 0); CP_COMMIT();
    issue(1, 1); CP_COMMIT();

    for (int ck = 0; ck < 16; ck++) {
        const int st = ck % 3;
        if (ck + 2 < 16) issue(ck + 2, (ck + 2) % 3);
        CP_COMMIT();                 // possibly empty group (tail)
        CP_WAIT(2);
        __syncthreads();

        const uint32_t bAhi = sb + st * G_STAGE;
        const uint32_t bAlo = bAhi + 16384;
        const uint32_t bBhi = bAhi + 32768;
        const uint32_t bBlo = bAhi + 49152;

        const int a_row = lane & 15, a_u = lane >> 4;
        const int b_r   = (lane & 7) + ((lane >> 4) << 3);
        const int b_u   = (lane >> 3) & 1;

#pragma unroll
        for (int ks = 0; ks < 4; ks++) {
            uint32_t ah[4][4], al[4][4], bh[4][2], bl[4][2];
#pragma unroll
            for (int mt = 0; mt < 4; mt++) {
                uint32_t off = SWZ128((uint32_t)((wm * 64 + mt * 16 + a_row) * 128
                                                 + ks * 32 + a_u * 16));
                ldm_x4(ah[mt], bAhi + off);
                ldm_x4(al[mt], bAlo + off);
            }
#pragma unroll
            for (int ntp = 0; ntp < 2; ntp++) {
                uint32_t off = SWZ128((uint32_t)((wn * 32 + ntp * 16 + b_r) * 128
                                                 + ks * 32 + b_u * 16));
                uint32_t t4[4];
                ldm_x4(t4, bBhi + off);
                bh[2*ntp][0] = t4[0]; bh[2*ntp][1] = t4[1];
                bh[2*ntp+1][0] = t4[2]; bh[2*ntp+1][1] = t4[3];
                ldm_x4(t4, bBlo + off);
                bl[2*ntp][0] = t4[0]; bl[2*ntp][1] = t4[1];
                bl[2*ntp+1][0] = t4[2]; bl[2*ntp+1][1] = t4[3];
            }
#pragma unroll
            for (int mt = 0; mt < 4; mt++)
#pragma unroll
                for (int nt = 0; nt < 4; nt++) {
                    mma16816(acc[mt][nt], ah[mt], bh[nt]);
                    mma16816(acc[mt][nt], ah[mt], bl[nt]);
                    mma16816(acc[mt][nt], al[mt], bh[nt]);
                }
        }
        __syncthreads();
    }

    const int lr = lane >> 2, lc = (lane & 3) * 2;
#pragma unroll
    for (int mt = 0; mt < 4; mt++) {
#pragma unroll
        for (int nt = 0; nt < 4; nt++) {
            const int m = m0 + wm * 64 + mt * 16 + lr;
            const int n = n0 + wn * 32 + nt * 8 + lc;
            float c0 = acc[mt][nt][0], c1 = acc[mt][nt][1];
            float c2 = acc[mt][nt][2], c3 = acc[mt][nt][3];
            if (MODE == 0) {
                *(float2*)(out + (size_t)m * EE + n)       = make_float2(c0, c1);
                *(float2*)(out + (size_t)(m + 8) * EE + n) = make_float2(c2, c3);
            } else {
                float2 bs = *(const float2*)(bias + n);
                const int h = n >> 6, d = n & 63;
#pragma unroll
                for (int half = 0; half < 2; half++) {
                    const int mr = m + half * 8;
                    const int s = mr >> 1, b = mr & 1;   // BB == 2
                    const size_t idx = (((size_t)(b * HH + h)) * SQ + s) * DD + d;
                    float va = (half ? c2 : c0) + bs.x;
                    float vb = (half ? c3 : c1) + bs.y;
                    if (MODE == 1) {
                        *(float2*)(out + idx) = make_float2(va, vb);
                    } else {   // MODE 2: bf16 hi/lo
                        __nv_bfloat16 ha = __float2bfloat16(va);
                        __nv_bfloat16 hb = __float2bfloat16(vb);
                        float la = va - __bfloat162float(ha);
                        float lb = vb - __bfloat162float(hb);
                        uint32_t hp = ((uint32_t)*(uint16_t*)&hb << 16) | *(uint16_t*)&ha;
                        *(uint32_t*)(ohi + idx) = hp;
                        *(uint32_t*)(olo + idx) = pack_bf16x2(la, lb);
                    }
                }
            }
        }
    }
}

// ---------------- RoPE + bf16 hi/lo convert (Q scaled) ----------------------
__global__ __launch_bounds__(256)
void rope_cvt(const float* __restrict__ cosT, const float* __restrict__ sinT)
{
    int gid = blockIdx.x * 256 + threadIdx.x;   // BB*HH*SQ*32 threads
    int d   = gid & 31;
    int row = gid >> 5;                          // bh*SQ + s
    int s   = row & (SQ - 1);
    size_t base = (size_t)row * DD;
    float c1 = cosT[s*DD + d],      s1 = sinT[s*DD + d];
    float c2 = cosT[s*DD + d + 32], s2 = sinT[s*DD + d + 32];

    float q1 = g_Q[base + d], q2 = g_Q[base + d + 32];
    float k1 = g_K[base + d], k2 = g_K[base + d + 32];
    float qa = (q1*c1 - q2*s1) * SCALE;
    float qb = (q2*c2 + q1*s2) * SCALE;
    float ka = k1*c1 - k2*s1;
    float kb = k2*c2 + k1*s2;

    __nv_bfloat16 h;
    h = __float2bfloat16(qa); g_Qhi[base+d] = h;
    g_Qlo[base+d] = __float2bfloat16(qa - __bfloat162float(h));
    h = __float2bfloat16(qb); g_Qhi[base+d+32] = h;
    g_Qlo[base+d+32] = __float2bfloat16(qb - __bfloat162float(h));
    h = __float2bfloat16(ka); g_Khi[base+d] = h;
    g_Klo[base+d] = __float2bfloat16(ka - __bfloat162float(h));
    h = __float2bfloat16(kb); g_Khi[base+d+32] = h;
    g_Klo[base+d+32] = __float2bfloat16(kb - __bfloat162float(h));
}

// ---------------- Flash attention on mma.sync (causal) ----------------------
// CTA: 128 q-rows, 8 warps (one m16 band each). K/V tiles 64 wide, cp.async
// double-buffered. 3-term hi/lo split on both Q.K^T and P.V; P stays in regs.
#define ATT_SMEM 65536   // 2 stages x 32KB (Khi,Klo,Vhi,Vlo @ 8KB each)

__global__ __launch_bounds__(256, 1)
void attn_mma()
{
    extern __shared__ char dsm[];
    const uint32_t sb = smem_u32(dsm);
    const int tid = threadIdx.x, wid = tid >> 5, lane = tid & 31;
    const int bh  = blockIdx.y;                       // b*HH + h
    const int qi  = gridDim.x - 1 - (int)blockIdx.x;  // heavy tiles first
    const int s0  = qi * 128;
    const int njt = 2 * qi + 2;
    const int lr  = lane >> 2, lc = (lane & 3) * 2;

    const size_t headoff = (size_t)bh * SQ * DD;

    // ---- stage Q (hi at sb, lo at sb+16384; 16KB each), then to registers
#pragma unroll
    for (int i = 0; i < 4; i++) {
        int cid = tid + 256 * i;                 // 0..1023
        int row = cid >> 3, seg = cid & 7;
        uint32_t off = SWZ128((uint32_t)(row * 128 + seg * 16));
        const size_t g = headoff + (size_t)(s0 + row) * DD + seg * 8;
        cp_async16(sb + off,         g_Qhi + g);
        cp_async16(sb + 16384 + off, g_Qlo + g);
    }
    CP_COMMIT(); CP_WAIT(0); __syncthreads();

    uint32_t qh[4][4], ql[4][4];
    {
        const int arow = lane & 15, au = lane >> 4;
#pragma unroll
        for (int kc = 0; kc < 4; kc++) {
            uint32_t off = SWZ128((uint32_t)((wid * 16 + arow) * 128 + kc * 32 + au * 16));
            ldm_x4(qh[kc], sb + off);
            ldm_x4(ql[kc], sb + 16384 + off);
        }
    }
    __syncthreads();   // done reading Q smem before K/V overwrite

    auto issueKV = [&](int jt, int st) {
        const uint32_t base = sb + st * 32768;
        const size_t gofs = headoff + (size_t)(jt * 64) * DD;
#pragma unroll
        for (int i = 0; i < 2; i++) {
            int cid = tid + 256 * i;             // 0..511
            int row = cid >> 3, seg = cid & 7;
            uint32_t off = SWZ128((uint32_t)(row * 128 + seg * 16));
            const size_t g = gofs + (size_t)row * DD + seg * 8;
            cp_async16(base +         off, g_Khi + g);
            cp_async16(base + 8192  + off, g_Klo + g);
            cp_async16(base + 16384 + off, g_Vhi + g);
            cp_async16(base + 24576 + off, g_Vlo + g);
        }
    };

    float m_[2] = {-1e30f, -1e30f}, l_[2] = {0.f, 0.f};
    float o[8][4];
#pragma unroll
    for (int nt = 0; nt < 8; nt++)
#pragma unroll
        for (int k = 0; k < 4; k++) o[nt][k] = 0.f;

    issueKV(0, 0); CP_COMMIT();

    for (int jt = 0; jt < njt; jt++) {
        const int st = jt & 1;
        if (jt + 1 < njt) { issueKV(jt + 1, st ^ 1); CP_COMMIT(); CP_WAIT(1); }
        else              { CP_WAIT(0); }
        __syncthreads();

        const uint32_t bK = sb + st * 32768;

        // ---- scores = Q . K^T (3-term)
        float sc[8][4];
#pragma unroll
        for (int nt = 0; nt < 8; nt++)
#pragma unroll
            for (int k = 0; k < 4; k++) sc[nt][k] = 0.f;
        {
            const int brow = lane & 7, bu = (lane >> 3) & 1;
#pragma unroll
            for (int kc = 0; kc < 4; kc++) {
                uint32_t kbh[8][2], kbl[8][2];
#pragma unroll
                for (int nt = 0; nt < 8; nt++) {
                    uint32_t off = SWZ128((uint32_t)((nt * 8 + brow) * 128 + kc * 32 + bu * 16));
                    ldm_x2(kbh[nt], bK + off);
                    ldm_x2(kbl[nt], bK + 8192 + off);
                }
#pragma unroll
                for (int nt = 0; nt < 8; nt++) {
                    mma16816(sc[nt], qh[kc], kbh[nt]);
                    mma16816(sc[nt], qh[kc], kbl[nt]);
                    mma16816(sc[nt], ql[kc], kbh[nt]);
                }
            }
        }

        // ---- causal mask (only boundary tiles)
        if (jt >= 2 * qi) {
            const int t0 = jt * 64;
            const int r0 = s0 + wid * 16 + lr;
#pragma unroll
            for (int nt = 0; nt < 8; nt++) {
                int t = t0 + nt * 8 + lc;
                if (t     > r0)     sc[nt][0] = -1e30f;
                if (t + 1 > r0)     sc[nt][1] = -1e30f;
                if (t     > r0 + 8) sc[nt][2] = -1e30f;
                if (t + 1 > r0 + 8) sc[nt][3] = -1e30f;
            }
        }

        // ---- online softmax (rows lr and lr+8)
        float mx0 = -1e30f, mx1 = -1e30f;
#pragma unroll
        for (int nt = 0; nt < 8; nt++) {
            mx0 = fmaxf(mx0, fmaxf(sc[nt][0], sc[nt][1]));
            mx1 = fmaxf(mx1, fmaxf(sc[nt][2], sc[nt][3]));
        }
        mx0 = fmaxf(mx0, __shfl_xor_sync(0xffffffffu, mx0, 1));
        mx0 = fmaxf(mx0, __shfl_xor_sync(0xffffffffu, mx0, 2));
        mx1 = fmaxf(mx1, __shfl_xor_sync(0xffffffffu, mx1, 1));
        mx1 = fmaxf(mx1, __shfl_xor_sync(0xffffffffu, mx1, 2));
        float mn0 = fmaxf(m_[0], mx0), mn1 = fmaxf(m_[1], mx1);
        float corr0 = __expf(m_[0] - mn0), corr1 = __expf(m_[1] - mn1);
        m_[0] = mn0; m_[1] = mn1;
        float su0 = 0.f, su1 = 0.f;
#pragma unroll
        for (int nt = 0; nt < 8; nt++) {
            sc[nt][0] = __expf(sc[nt][0] - mn0);
            sc[nt][1] = __expf(sc[nt][1] - mn0);
            sc[nt][2] = __expf(sc[nt][2] - mn1);
            sc[nt][3] = __expf(sc[nt][3] - mn1);
            su0 += sc[nt][0] + sc[nt][1];
            su1 += sc[nt][2] + sc[nt][3];
        }
        su0 += __shfl_xor_sync(0xffffffffu, su0, 1);
        su0 += __shfl_xor_sync(0xffffffffu, su0, 2);
        su1 += __shfl_xor_sync(0xffffffffu, su1, 1);
        su1 += __shfl_xor_sync(0xffffffffu, su1, 2);
        l_[0] = l_[0] * corr0 + su0;
        l_[1] = l_[1] * corr1 + su1;
#pragma unroll
        for (int nt = 0; nt < 8; nt++) {
            o[nt][0] *= corr0; o[nt][1] *= corr0;
            o[nt][2] *= corr1; o[nt][3] *= corr1;
        }

        // ---- P -> bf16 hi/lo A-fragments (exact truncation split, in regs)
        uint32_t pah[4][4], pal[4][4];
#pragma unroll
        for (int c = 0; c < 4; c++) {
#pragma unroll
            for (int q = 0; q < 4; q++) {
                const int nt = 2 * c + (q >> 1);          // tile pair
                const int e0 = (q & 1) * 2;               // c0/c1 or c2/c3
                float a = sc[nt][e0], b = sc[nt][e0 + 1];
                uint32_t ua = __float_as_uint(a), ub = __float_as_uint(b);
                uint32_t hp = __byte_perm(ua, ub, 0x7632); // {a.hi16, b.hi16}
                float la = a - __uint_as_float(ua & 0xFFFF0000u);
                float lb = b - __uint_as_float(ub & 0xFFFF0000u);
                // frag reg index: a0=(r,c) a1=(r+8,c) a2=(r,c+8) a3=(r+8,c+8)
                const int ri = (q & 1) + ((q >> 1) << 1);  // 0:a0 1:a1 2:a2 3:a3
                pah[c][ri] = hp;
                pal[c][ri] = pack_bf16x2(la, lb);
            }
        }

        // ---- O += P . V (3-term), V via ldmatrix.trans
        const uint32_t bV = bK + 16384;
        {
            const int vrow = lane & 15;
#pragma unroll
            for (int tc = 0; tc < 4; tc++) {
                uint32_t vbh[8][2], vbl[8][2];
#pragma unroll
                for (int nt = 0; nt < 8; nt++) {
                    uint32_t off = SWZ128((uint32_t)((tc * 16 + vrow) * 128 + nt * 16));
                    ldm_x2t(vbh[nt], bV + off);
                    ldm_x2t(vbl[nt], bV + 8192 + off);
                }
#pragma unroll
                for (int nt = 0; nt < 8; nt++) {
                    mma16816(o[nt], pah[tc], vbh[nt]);
                    mma16816(o[nt], pah[tc], vbl[nt]);
                    mma16816(o[nt], pal[tc], vbh[nt]);
                }
            }
        }
        __syncthreads();
    }

    // ---- normalize + write [s][b][e]
    const float inv0 = 1.f / l_[0], inv1 = 1.f / l_[1];
    const int b = bh >> 4, h = bh & 15;
    const int sA = s0 + wid * 16 + lr;
#pragma unroll
    for (int nt = 0; nt < 8; nt++) {
        const int d = nt * 8 + lc;
        *(float2*)&g_A[((size_t)sA * BB + b) * EE + h * DD + d] =
            make_float2(o[nt][0] * inv0, o[nt][1] * inv0);
        *(float2*)&g_A[((size_t)(sA + 8) * BB + b) * EE + h * DD + d] =
            make_float2(o[nt][2] * inv1, o[nt][3] * inv1);
    }
}

// ---------------- RMSNorm fused with hi/lo split ----------------------------
// reads g_A row, writes normalized bf16 hi/lo directly to g_xhi/g_xlo
__global__ __launch_bounds__(256)
void rms_cvt(const float* __restrict__ w)
{
    const int r = blockIdx.x;
    const float* a = g_A + (size_t)r * EE;
    const int tid = threadIdx.x;
    float4 v = ((const float4*)a)[tid];          // EE/4 == 256 == blockDim
    float ss = v.x*v.x + v.y*v.y + v.z*v.z + v.w*v.w;
#pragma unroll
    for (int ofs = 16; ofs; ofs >>= 1) ss += __shfl_xor_sync(0xffffffffu, ss, ofs);
    __shared__ float red[8];
    if ((tid & 31) == 0) red[tid >> 5] = ss;
    __syncthreads();
    float tot = 0.f;
#pragma unroll
    for (int i = 0; i < 8; i++) tot += red[i];
    float rstd = rsqrtf(tot * (1.f / EE) + RMS_EPS);
    float4 wv = ((const float4*)w)[tid];
    float4 ov = { v.x*rstd*wv.x, v.y*rstd*wv.y, v.z*rstd*wv.z, v.w*rstd*wv.w };
    uint2 uh, ul;
    split4(ov, uh, ul);
    ((uint2*)(g_xhi + (size_t)r * EE))[tid] = uh;
    ((uint2*)(g_xlo + (size_t)r * EE))[tid] = ul;
}

// ---------------- launch -----------------------------------------------------
extern "C" void kernel_launch(void* const* d_in, const int* in_sizes, int n_in,
                              void* d_out, int out_size)
{
    const float* x    = (const float*)d_in[0];
    // d_in[1] = attn_mask (pure causal, implemented analytically)
    const float* cosT = (const float*)d_in[2];
    const float* sinT = (const float*)d_in[3];
    const float* Wq   = (const float*)d_in[4];
    const float* bq   = (const float*)d_in[5];
    const float* Wk   = (const float*)d_in[6];
    const float* bk   = (const float*)d_in[7];
    const float* Wv   = (const float*)d_in[8];
    const float* bv   = (const float*)d_in[9];
    const float* Wo   = (const float*)d_in[10];
    const float* nw   = (const float*)d_in[11];

    float *pQ, *pK;
    __nv_bfloat16 *pxh, *pxl, *pVhi, *pVlo;
    __nv_bfloat16 *pwqh, *pwql, *pwkh, *pwkl, *pwvh, *pwvl, *pwoh, *pwol;
    cudaGetSymbolAddress((void**)&pQ, g_Q);
    cudaGetSymbolAddress((void**)&pK, g_K);
    cudaGetSymbolAddress((void**)&pxh, g_xhi);
    cudaGetSymbolAddress((void**)&pxl, g_xlo);
    cudaGetSymbolAddress((void**)&pVhi, g_Vhi);
    cudaGetSymbolAddress((void**)&pVlo, g_Vlo);
    cudaGetSymbolAddress((void**)&pwqh, g_wqhi);
    cudaGetSymbolAddress((void**)&pwql, g_wqlo);
    cudaGetSymbolAddress((void**)&pwkh, g_wkhi);
    cudaGetSymbolAddress((void**)&pwkl, g_wklo);
    cudaGetSymbolAddress((void**)&pwvh, g_wvhi);
    cudaGetSymbolAddress((void**)&pwvl, g_wvlo);
    cudaGetSymbolAddress((void**)&pwoh, g_wohi);
    cudaGetSymbolAddress((void**)&pwol, g_wolo);

    cudaFuncSetAttribute(gemm_mma<0>, cudaFuncAttributeMaxDynamicSharedMemorySize, G_SMEM);
    cudaFuncSetAttribute(gemm_mma<1>, cudaFuncAttributeMaxDynamicSharedMemorySize, G_SMEM);
    cudaFuncSetAttribute(gemm_mma<2>, cudaFuncAttributeMaxDynamicSharedMemorySize, G_SMEM);
    cudaFuncSetAttribute(attn_mma,   cudaFuncAttributeMaxDynamicSharedMemorySize, ATT_SMEM);

    const int n4x = MM * EE / 4;   // 1,048,576
    const int n4w = EE * EE / 4;   // 262,144
    dim3 ggrid(EE/128, MM/128);    // (8, 32)

    cvt_hilo<<<n4x/256, 256>>>(x, pxh, pxl, n4x);
    cvt_w4<<<n4w/256, 256>>>(Wq, Wk, Wv, Wo);

    gemm_mma<1><<<ggrid, 256, G_SMEM>>>(pxh, pxl, pwqh, pwql, bq, pQ, nullptr, nullptr);
    gemm_mma<1><<<ggrid, 256, G_SMEM>>>(pxh, pxl, pwkh, pwkl, bk, pK, nullptr, nullptr);
    gemm_mma<2><<<ggrid, 256, G_SMEM>>>(pxh, pxl, pwvh, pwvl, bv, nullptr, pVhi, pVlo);

    rope_cvt<<<(BB*HH*SQ*32)/256, 256>>>(cosT, sinT);

    attn_mma<<<dim3(SQ/128, BB*HH), 256, ATT_SMEM>>>();

    rms_cvt<<<MM, 256>>>(nw);

    gemm_mma<0><<<ggrid, 256, G_SMEM>>>(pxh, pxl, pwoh, pwol, nullptr, (float*)d_out, nullptr, nullptr);
}

// round 16
// speedup vs baseline: 4.1355x; 1.0043x over previous
#include <cuda_runtime.h>
#include <cuda_bf16.h>
#include <cstdint>

#define SQ 2048
#define BB 2
#define EE 1024
#define HH 16
#define DD 64
#define MM (SQ*BB)              // 4096 rows (s,b)
#define SCALE 0.125f            // 64^-0.5
#define L2E 1.44269504088896340736f
#define RMS_EPS 1e-6f

// ---------------- scratch (device globals: no runtime allocation) ----------
__device__ float g_Q[(size_t)BB*HH*SQ*DD];   // [b][h][s][d] fp32 (pre-RoPE)
__device__ float g_K[(size_t)BB*HH*SQ*DD];
__device__ float g_A[(size_t)MM*EE];         // attention out, [s][b][e]
__device__ __nv_bfloat16 g_xhi[(size_t)MM*EE];
__device__ __nv_bfloat16 g_xlo[(size_t)MM*EE];
__device__ __nv_bfloat16 g_wqhi[(size_t)EE*EE], g_wqlo[(size_t)EE*EE];
__device__ __nv_bfloat16 g_wkhi[(size_t)EE*EE], g_wklo[(size_t)EE*EE];
__device__ __nv_bfloat16 g_wvhi[(size_t)EE*EE], g_wvlo[(size_t)EE*EE];
__device__ __nv_bfloat16 g_wohi[(size_t)EE*EE], g_wolo[(size_t)EE*EE];
// bf16 hi/lo Q,K,V in [b][h][s][d] for mma attention (Q pre-scaled by SCALE*log2e)
__device__ __nv_bfloat16 g_Qhi[(size_t)BB*HH*SQ*DD];
__device__ __nv_bfloat16 g_Qlo[(size_t)BB*HH*SQ*DD];
__device__ __nv_bfloat16 g_Khi[(size_t)BB*HH*SQ*DD];
__device__ __nv_bfloat16 g_Klo[(size_t)BB*HH*SQ*DD];
__device__ __nv_bfloat16 g_Vhi[(size_t)BB*HH*SQ*DD];
__device__ __nv_bfloat16 g_Vlo[(size_t)BB*HH*SQ*DD];

// ---------------- PTX helpers (plain sm_103-safe: no 'a' features) ----------
__device__ __forceinline__ uint32_t smem_u32(const void* p) {
    uint32_t a;
    asm("{ .reg .u64 t; cvta.to.shared.u64 t, %1; cvt.u32.u64 %0, t; }"
        : "=r"(a) : "l"(p));
    return a;
}

__device__ __forceinline__ void cp_async16(uint32_t smem, const void* g) {
    asm volatile("cp.async.cg.shared.global [%0], [%1], 16;"
                 :: "r"(smem), "l"(g) : "memory");
}
#define CP_COMMIT() asm volatile("cp.async.commit_group;" ::: "memory")
#define CP_WAIT(n)  asm volatile("cp.async.wait_group %0;" :: "n"(n) : "memory")

__device__ __forceinline__ void ldm_x4(uint32_t* r, uint32_t addr) {
    asm volatile("ldmatrix.sync.aligned.m8n8.x4.shared.b16 {%0,%1,%2,%3}, [%4];"
                 : "=r"(r[0]), "=r"(r[1]), "=r"(r[2]), "=r"(r[3]) : "r"(addr));
}
__device__ __forceinline__ void ldm_x4t(uint32_t* r, uint32_t addr) {
    asm volatile("ldmatrix.sync.aligned.m8n8.x4.trans.shared.b16 {%0,%1,%2,%3}, [%4];"
                 : "=r"(r[0]), "=r"(r[1]), "=r"(r[2]), "=r"(r[3]) : "r"(addr));
}

__device__ __forceinline__ void mma16816(float* c, const uint32_t* a, const uint32_t* b) {
    asm volatile(
        "mma.sync.aligned.m16n8k16.row.col.f32.bf16.bf16.f32 "
        "{%0,%1,%2,%3}, {%4,%5,%6,%7}, {%8,%9}, {%0,%1,%2,%3};"
        : "+f"(c[0]), "+f"(c[1]), "+f"(c[2]), "+f"(c[3])
        : "r"(a[0]), "r"(a[1]), "r"(a[2]), "r"(a[3]), "r"(b[0]), "r"(b[1]));
}

// low half <- lo, high half <- hi
__device__ __forceinline__ uint32_t pack_bf16x2(float lo, float hi) {
    uint32_t r;
    asm("cvt.rn.bf16x2.f32 %0, %1, %2;" : "=r"(r) : "f"(hi), "f"(lo));
    return r;
}

#define SWZ128(off) ((off) ^ (((off) >> 3) & 0x70))

// ---------------- fp32 -> (hi, lo) bf16 split -------------------------------
__device__ __forceinline__ void split4(float4 v, uint2& uh, uint2& ul) {
    float vv[4] = {v.x, v.y, v.z, v.w};
    __nv_bfloat16 h[4], l[4];
#pragma unroll
    for (int j = 0; j < 4; j++) {
        h[j] = __float2bfloat16(vv[j]);
        l[j] = __float2bfloat16(vv[j] - __bfloat162float(h[j]));
    }
    __nv_bfloat162 h01, h23, l01, l23;
    h01.x = h[0]; h01.y = h[1]; h23.x = h[2]; h23.y = h[3];
    l01.x = l[0]; l01.y = l[1]; l23.x = l[2]; l23.y = l[3];
    uh.x = *(uint32_t*)&h01; uh.y = *(uint32_t*)&h23;
    ul.x = *(uint32_t*)&l01; ul.y = *(uint32_t*)&l23;
}

__global__ __launch_bounds__(256)
void cvt_hilo(const float* __restrict__ x, __nv_bfloat16* __restrict__ hi,
              __nv_bfloat16* __restrict__ lo, int n4)
{
    int i = blockIdx.x * 256 + threadIdx.x;
    if (i >= n4) return;
    uint2 uh, ul;
    split4(((const float4*)x)[i], uh, ul);
    ((uint2*)hi)[i] = uh;
    ((uint2*)lo)[i] = ul;
}

__global__ __launch_bounds__(256)
void cvt_w4(const float* __restrict__ wq, const float* __restrict__ wk,
            const float* __restrict__ wv, const float* __restrict__ wo)
{
    int i = blockIdx.x * 256 + threadIdx.x;    // 0 .. EE*EE/4-1
    uint2 uh, ul;
    split4(((const float4*)wq)[i], uh, ul);
    ((uint2*)g_wqhi)[i] = uh; ((uint2*)g_wqlo)[i] = ul;
    split4(((const float4*)wk)[i], uh, ul);
    ((uint2*)g_wkhi)[i] = uh; ((uint2*)g_wklo)[i] = ul;
    split4(((const float4*)wv)[i], uh, ul);
    ((uint2*)g_wvhi)[i] = uh; ((uint2*)g_wvlo)[i] = ul;
    split4(((const float4*)wo)[i], uh, ul);
    ((uint2*)g_wohi)[i] = uh; ((uint2*)g_wolo)[i] = ul;
}

// ---------------- mma.sync GEMM: C = A * W^T (+bias) ------------------------
// Tile 64x128, 128 threads (4 warps in N), 2 CTAs/SM. K-chunk 64, 16 chunks,
// 2-stage cp.async pipeline, ONE sync per chunk. SWZ128 smem.
// MODE 0: fp32 row-major (no bias). MODE 1: fp32 BHSD + bias. MODE 2: bf16 hi/lo BHSD + bias.
#define G_STAGE 49152                   // Ahi 8K, Alo 8K, Bhi 16K, Blo 16K
#define G_SMEM  (2 * G_STAGE)           // 98304

template<int MODE>
__global__ __launch_bounds__(128, 2)
void gemm_mma(const __nv_bfloat16* __restrict__ Ahi, const __nv_bfloat16* __restrict__ Alo,
              const __nv_bfloat16* __restrict__ Bhi, const __nv_bfloat16* __restrict__ Blo,
              const float* __restrict__ bias, float* __restrict__ out,
              __nv_bfloat16* __restrict__ ohi, __nv_bfloat16* __restrict__ olo)
{
    extern __shared__ char dsm[];
    const uint32_t sb = smem_u32(dsm);
    const int tid  = threadIdx.x;
    const int wn   = tid >> 5, lane = tid & 31;   // 4 warps across N
    const int m0   = blockIdx.y * 64;
    const int n0   = blockIdx.x * 128;

    float acc[4][4][4];
#pragma unroll
    for (int i = 0; i < 4; i++)
#pragma unroll
        for (int j = 0; j < 4; j++)
#pragma unroll
            for (int k = 0; k < 4; k++) acc[i][j][k] = 0.f;

    auto issue = [&](int ck, int st) {
        const uint32_t base = sb + st * G_STAGE;
#pragma unroll
        for (int i = 0; i < 4; i++) {              // A hi/lo: 64 rows
            const int cid = i * 128 + tid;         // 0..511
            const int row = cid >> 3, seg = cid & 7;
            uint32_t off = SWZ128((uint32_t)(row * 128 + seg * 16));
            const size_t g = (size_t)(m0 + row) * EE + ck * 64 + seg * 8;
            cp_async16(base + off,        Ahi + g);
            cp_async16(base + 8192 + off, Alo + g);
        }
#pragma unroll
        for (int i = 0; i < 8; i++) {              // B hi/lo: 128 rows
            const int cid = i * 128 + tid;         // 0..1023
            const int row = cid >> 3, seg = cid & 7;
            uint32_t off = SWZ128((uint32_t)(row * 128 + seg * 16));
            const size_t g = (size_t)(n0 + row) * EE + ck * 64 + seg * 8;
            cp_async16(base + 16384 + off, Bhi + g);
            cp_async16(base + 32768 + off, Blo + g);
        }
    };

    issue(0, 0); CP_COMMIT();

    const int a_row = lane & 15, a_u = lane >> 4;
    const int b_r   = (lane & 7) + ((lane >> 4) << 3);
    const int b_u   = (lane >> 3) & 1;

    for (int ck = 0; ck < 16; ck++) {
        const int st = ck & 1;
        CP_WAIT(0);
        __syncthreads();
        if (ck + 1 < 16) issue(ck + 1, st ^ 1);
        CP_COMMIT();

        const uint32_t bAhi = sb + st * G_STAGE;
        const uint32_t bAlo = bAhi + 8192;
        const uint32_t bBhi = bAhi + 16384;
        const uint32_t bBlo = bAhi + 32768;

#pragma unroll
        for (int ks = 0; ks < 4; ks++) {
            uint32_t ah[4][4], al[4][4], bh[4][2], bl[4][2];
#pragma unroll
            for (int mt = 0; mt < 4; mt++) {
                uint32_t off = SWZ128((uint32_t)((mt * 16 + a_row) * 128
                                                 + ks * 32 + a_u * 16));
                ldm_x4(ah[mt], bAhi + off);
                ldm_x4(al[mt], bAlo + off);
            }
#pragma unroll
            for (int ntp = 0; ntp < 2; ntp++) {
                uint32_t off = SWZ128((uint32_t)((wn * 32 + ntp * 16 + b_r) * 128
                                                 + ks * 32 + b_u * 16));
                uint32_t t4[4];
                ldm_x4(t4, bBhi + off);
                bh[2*ntp][0] = t4[0]; bh[2*ntp][1] = t4[1];
                bh[2*ntp+1][0] = t4[2]; bh[2*ntp+1][1] = t4[3];
                ldm_x4(t4, bBlo + off);
                bl[2*ntp][0] = t4[0]; bl[2*ntp][1] = t4[1];
                bl[2*ntp+1][0] = t4[2]; bl[2*ntp+1][1] = t4[3];
            }
#pragma unroll
            for (int mt = 0; mt < 4; mt++)
#pragma unroll
                for (int nt = 0; nt < 4; nt++) {
                    mma16816(acc[mt][nt], ah[mt], bh[nt]);
                    mma16816(acc[mt][nt], ah[mt], bl[nt]);
                    mma16816(acc[mt][nt], al[mt], bh[nt]);
                }
        }
    }

    const int lr = lane >> 2, lc = (lane & 3) * 2;
#pragma unroll
    for (int mt = 0; mt < 4; mt++) {
#pragma unroll
        for (int nt = 0; nt < 4; nt++) {
            const int m = m0 + mt * 16 + lr;
            const int n = n0 + wn * 32 + nt * 8 + lc;
            float c0 = acc[mt][nt][0], c1 = acc[mt][nt][1];
            float c2 = acc[mt][nt][2], c3 = acc[mt][nt][3];
            if (MODE == 0) {
                *(float2*)(out + (size_t)m * EE + n)       = make_float2(c0, c1);
                *(float2*)(out + (size_t)(m + 8) * EE + n) = make_float2(c2, c3);
            } else {
                float2 bs = *(const float2*)(bias + n);
                const int h = n >> 6, d = n & 63;
#pragma unroll
                for (int half = 0; half < 2; half++) {
                    const int mr = m + half * 8;
                    const int s = mr >> 1, b = mr & 1;   // BB == 2
                    const size_t idx = (((size_t)(b * HH + h)) * SQ + s) * DD + d;
                    float va = (half ? c2 : c0) + bs.x;
                    float vb = (half ? c3 : c1) + bs.y;
                    if (MODE == 1) {
                        *(float2*)(out + idx) = make_float2(va, vb);
                    } else {   // MODE 2: bf16 hi/lo
                        __nv_bfloat16 ha = __float2bfloat16(va);
                        __nv_bfloat16 hb = __float2bfloat16(vb);
                        float la = va - __bfloat162float(ha);
                        float lb = vb - __bfloat162float(hb);
                        uint32_t hp = ((uint32_t)*(uint16_t*)&hb << 16) | *(uint16_t*)&ha;
                        *(uint32_t*)(ohi + idx) = hp;
                        *(uint32_t*)(olo + idx) = pack_bf16x2(la, lb);
                    }
                }
            }
        }
    }
}

// ---------------- RoPE + bf16 hi/lo convert (Q scaled by SCALE*log2e) -------
__global__ __launch_bounds__(256)
void rope_cvt(const float* __restrict__ cosT, const float* __restrict__ sinT)
{
    int gid = blockIdx.x * 256 + threadIdx.x;   // BB*HH*SQ*32 threads
    int d   = gid & 31;
    int row = gid >> 5;                          // bh*SQ + s
    int s   = row & (SQ - 1);
    size_t base = (size_t)row * DD;
    float c1 = cosT[s*DD + d],      s1 = sinT[s*DD + d];
    float c2 = cosT[s*DD + d + 32], s2 = sinT[s*DD + d + 32];

    float q1 = g_Q[base + d], q2 = g_Q[base + d + 32];
    float k1 = g_K[base + d], k2 = g_K[base + d + 32];
    const float QS = SCALE * L2E;
    float qa = (q1*c1 - q2*s1) * QS;
    float qb = (q2*c2 + q1*s2) * QS;
    float ka = k1*c1 - k2*s1;
    float kb = k2*c2 + k1*s2;

    __nv_bfloat16 h;
    h = __float2bfloat16(qa); g_Qhi[base+d] = h;
    g_Qlo[base+d] = __float2bfloat16(qa - __bfloat162float(h));
    h = __float2bfloat16(qb); g_Qhi[base+d+32] = h;
    g_Qlo[base+d+32] = __float2bfloat16(qb - __bfloat162float(h));
    h = __float2bfloat16(ka); g_Khi[base+d] = h;
    g_Klo[base+d] = __float2bfloat16(ka - __bfloat162float(h));
    h = __float2bfloat16(kb); g_Khi[base+d+32] = h;
    g_Klo[base+d+32] = __float2bfloat16(kb - __bfloat162float(h));
}

// ---------------- Flash attention on mma.sync (causal) ----------------------
// CTA: 128 q-rows, 8 warps. K/V tiles 64 wide, 2-stage cp.async, ONE sync
// per tile. Scores in log2 domain (exp2f softmax). P stays in registers.
#define ATT_SMEM 65536   // 2 stages x 32KB (Khi,Klo,Vhi,Vlo @ 8KB each)

__global__ __launch_bounds__(256, 1)
void attn_mma()
{
    extern __shared__ char dsm[];
    const uint32_t sb = smem_u32(dsm);
    const int tid = threadIdx.x, wid = tid >> 5, lane = tid & 31;
    const int bh  = blockIdx.y;                       // b*HH + h
    const int qi  = gridDim.x - 1 - (int)blockIdx.x;  // heavy tiles first
    const int s0  = qi * 128;
    const int njt = 2 * qi + 2;
    const int lr  = lane >> 2, lc = (lane & 3) * 2;

    const size_t headoff = (size_t)bh * SQ * DD;

    // ---- stage Q (hi at sb, lo at sb+16384), then to registers
#pragma unroll
    for (int i = 0; i < 4; i++) {
        int cid = tid + 256 * i;                 // 0..1023
        int row = cid >> 3, seg = cid & 7;
        uint32_t off = SWZ128((uint32_t)(row * 128 + seg * 16));
        const size_t g = headoff + (size_t)(s0 + row) * DD + seg * 8;
        cp_async16(sb + off,         g_Qhi + g);
        cp_async16(sb + 16384 + off, g_Qlo + g);
    }
    CP_COMMIT(); CP_WAIT(0); __syncthreads();

    uint32_t qh[4][4], ql[4][4];
    {
        const int arow = lane & 15, au = lane >> 4;
#pragma unroll
        for (int kc = 0; kc < 4; kc++) {
            uint32_t off = SWZ128((uint32_t)((wid * 16 + arow) * 128 + kc * 32 + au * 16));
            ldm_x4(qh[kc], sb + off);
            ldm_x4(ql[kc], sb + 16384 + off);
        }
    }
    __syncthreads();   // done reading Q smem before K/V overwrite

    auto issueKV = [&](int jt, int st) {
        const uint32_t base = sb + st * 32768;
        const size_t gofs = headoff + (size_t)(jt * 64) * DD;
#pragma unroll
        for (int i = 0; i < 2; i++) {
            int cid = tid + 256 * i;             // 0..511
            int row = cid >> 3, seg = cid & 7;
            uint32_t off = SWZ128((uint32_t)(row * 128 + seg * 16));
            const size_t g = gofs + (size_t)row * DD + seg * 8;
            cp_async16(base +         off, g_Khi + g);
            cp_async16(base + 8192  + off, g_Klo + g);
            cp_async16(base + 16384 + off, g_Vhi + g);
            cp_async16(base + 24576 + off, g_Vlo + g);
        }
    };

    float m_[2] = {-1e30f, -1e30f}, l_[2] = {0.f, 0.f};
    float o[8][4];
#pragma unroll
    for (int nt = 0; nt < 8; nt++)
#pragma unroll
        for (int k = 0; k < 4; k++) o[nt][k] = 0.f;

    issueKV(0, 0); CP_COMMIT();

    const int b_r = (lane & 7) + ((lane >> 4) << 3);
    const int b_u = (lane >> 3) & 1;
    const int v_r = (lane & 7) + (((lane >> 3) & 1) << 3);
    const int v_c = (lane >> 4);

    for (int jt = 0; jt < njt; jt++) {
        const int st = jt & 1;
        CP_WAIT(0);
        __syncthreads();
        if (jt + 1 < njt) issueKV(jt + 1, st ^ 1);
        CP_COMMIT();

        const uint32_t bK = sb + st * 32768;

        // ---- scores = Q . K^T (3-term), in log2 domain
        float sc[8][4];
#pragma unroll
        for (int nt = 0; nt < 8; nt++)
#pragma unroll
            for (int k = 0; k < 4; k++) sc[nt][k] = 0.f;
        {
#pragma unroll
            for (int kc = 0; kc < 4; kc++) {
                uint32_t kbh[8][2], kbl[8][2];
#pragma unroll
                for (int p = 0; p < 4; p++) {
                    uint32_t off = SWZ128((uint32_t)((p * 16 + b_r) * 128 + kc * 32 + b_u * 16));
                    uint32_t t4[4];
                    ldm_x4(t4, bK + off);
                    kbh[2*p][0] = t4[0]; kbh[2*p][1] = t4[1];
                    kbh[2*p+1][0] = t4[2]; kbh[2*p+1][1] = t4[3];
                    ldm_x4(t4, bK + 8192 + off);
                    kbl[2*p][0] = t4[0]; kbl[2*p][1] = t4[1];
                    kbl[2*p+1][0] = t4[2]; kbl[2*p+1][1] = t4[3];
                }
#pragma unroll
                for (int nt = 0; nt < 8; nt++) {
                    mma16816(sc[nt], qh[kc], kbh[nt]);
                    mma16816(sc[nt], qh[kc], kbl[nt]);
                    mma16816(sc[nt], ql[kc], kbh[nt]);
                }
            }
        }

        // ---- causal mask (only boundary tiles)
        if (jt >= 2 * qi) {
            const int t0 = jt * 64;
            const int r0 = s0 + wid * 16 + lr;
#pragma unroll
            for (int nt = 0; nt < 8; nt++) {
                int t = t0 + nt * 8 + lc;
                if (t     > r0)     sc[nt][0] = -1e30f;
                if (t + 1 > r0)     sc[nt][1] = -1e30f;
                if (t     > r0 + 8) sc[nt][2] = -1e30f;
                if (t + 1 > r0 + 8) sc[nt][3] = -1e30f;
            }
        }

        // ---- online softmax (rows lr and lr+8), base-2
        float mx0 = -1e30f, mx1 = -1e30f;
#pragma unroll
        for (int nt = 0; nt < 8; nt++) {
            mx0 = fmaxf(mx0, fmaxf(sc[nt][0], sc[nt][1]));
            mx1 = fmaxf(mx1, fmaxf(sc[nt][2], sc[nt][3]));
        }
        mx0 = fmaxf(mx0, __shfl_xor_sync(0xffffffffu, mx0, 1));
        mx0 = fmaxf(mx0, __shfl_xor_sync(0xffffffffu, mx0, 2));
        mx1 = fmaxf(mx1, __shfl_xor_sync(0xffffffffu, mx1, 1));
        mx1 = fmaxf(mx1, __shfl_xor_sync(0xffffffffu, mx1, 2));
        float mn0 = fmaxf(m_[0], mx0), mn1 = fmaxf(m_[1], mx1);
        float corr0 = exp2f(m_[0] - mn0), corr1 = exp2f(m_[1] - mn1);
        m_[0] = mn0; m_[1] = mn1;
        float su0 = 0.f, su1 = 0.f;
#pragma unroll
        for (int nt = 0; nt < 8; nt++) {
            sc[nt][0] = exp2f(sc[nt][0] - mn0);
            sc[nt][1] = exp2f(sc[nt][1] - mn0);
            sc[nt][2] = exp2f(sc[nt][2] - mn1);
            sc[nt][3] = exp2f(sc[nt][3] - mn1);
            su0 += sc[nt][0] + sc[nt][1];
            su1 += sc[nt][2] + sc[nt][3];
        }
        su0 += __shfl_xor_sync(0xffffffffu, su0, 1);
        su0 += __shfl_xor_sync(0xffffffffu, su0, 2);
        su1 += __shfl_xor_sync(0xffffffffu, su1, 1);
        su1 += __shfl_xor_sync(0xffffffffu, su1, 2);
        l_[0] = l_[0] * corr0 + su0;
        l_[1] = l_[1] * corr1 + su1;
#pragma unroll
        for (int nt = 0; nt < 8; nt++) {
            o[nt][0] *= corr0; o[nt][1] *= corr0;
            o[nt][2] *= corr1; o[nt][3] *= corr1;
        }

        // ---- P -> bf16 hi/lo A-fragments (exact truncation split, in regs)
        uint32_t pah[4][4], pal[4][4];
#pragma unroll
        for (int c = 0; c < 4; c++) {
#pragma unroll
            for (int q = 0; q < 4; q++) {
                const int nt = 2 * c + (q >> 1);
                const int e0 = (q & 1) * 2;
                float a = sc[nt][e0], b = sc[nt][e0 + 1];
                uint32_t ua = __float_as_uint(a), ub = __float_as_uint(b);
                uint32_t hp = __byte_perm(ua, ub, 0x7632);
                float la = a - __uint_as_float(ua & 0xFFFF0000u);
                float lb = b - __uint_as_float(ub & 0xFFFF0000u);
                const int ri = (q & 1) + ((q >> 1) << 1);
                pah[c][ri] = hp;
                pal[c][ri] = pack_bf16x2(la, lb);
            }
        }

        // ---- O += P . V (3-term), V via ldmatrix.x4.trans (nt-pairs)
        const uint32_t bV = bK + 16384;
        {
#pragma unroll
            for (int tc = 0; tc < 4; tc++) {
                uint32_t vbh[8][2], vbl[8][2];
#pragma unroll
                for (int p = 0; p < 4; p++) {
                    uint32_t off = SWZ128((uint32_t)((tc * 16 + v_r) * 128
                                                     + p * 32 + v_c * 16));
                    uint32_t t4[4];
                    ldm_x4t(t4, bV + off);
                    vbh[2*p][0] = t4[0]; vbh[2*p][1] = t4[1];
                    vbh[2*p+1][0] = t4[2]; vbh[2*p+1][1] = t4[3];
                    ldm_x4t(t4, bV + 8192 + off);
                    vbl[2*p][0] = t4[0]; vbl[2*p][1] = t4[1];
                    vbl[2*p+1][0] = t4[2]; vbl[2*p+1][1] = t4[3];
                }
#pragma unroll
                for (int nt = 0; nt < 8; nt++) {
                    mma16816(o[nt], pah[tc], vbh[nt]);
                    mma16816(o[nt], pah[tc], vbl[nt]);
                    mma16816(o[nt], pal[tc], vbh[nt]);
                }
            }
        }
    }

    // ---- normalize + write [s][b][e]
    const float inv0 = 1.f / l_[0], inv1 = 1.f / l_[1];
    const int b = bh >> 4, h = bh & 15;
    const int sA = s0 + wid * 16 + lr;
#pragma unroll
    for (int nt = 0; nt < 8; nt++) {
        const int d = nt * 8 + lc;
        *(float2*)&g_A[((size_t)sA * BB + b) * EE + h * DD + d] =
            make_float2(o[nt][0] * inv0, o[nt][1] * inv0);
        *(float2*)&g_A[((size_t)(sA + 8) * BB + b) * EE + h * DD + d] =
            make_float2(o[nt][2] * inv1, o[nt][3] * inv1);
    }
}

// ---------------- RMSNorm fused with hi/lo split ----------------------------
__global__ __launch_bounds__(256)
void rms_cvt(const float* __restrict__ w)
{
    const int r = blockIdx.x;
    const float* a = g_A + (size_t)r * EE;
    const int tid = threadIdx.x;
    float4 v = ((const float4*)a)[tid];          // EE/4 == 256 == blockDim
    float ss = v.x*v.x + v.y*v.y + v.z*v.z + v.w*v.w;
#pragma unroll
    for (int ofs = 16; ofs; ofs >>= 1) ss += __shfl_xor_sync(0xffffffffu, ss, ofs);
    __shared__ float red[8];
    if ((tid & 31) == 0) red[tid >> 5] = ss;
    __syncthreads();
    float tot = 0.f;
#pragma unroll
    for (int i = 0; i < 8; i++) tot += red[i];
    float rstd = rsqrtf(tot * (1.f / EE) + RMS_EPS);
    float4 wv = ((const float4*)w)[tid];
    float4 ov = { v.x*rstd*wv.x, v.y*rstd*wv.y, v.z*rstd*wv.z, v.w*rstd*wv.w };
    uint2 uh, ul;
    split4(ov, uh, ul);
    ((uint2*)(g_xhi + (size_t)r * EE))[tid] = uh;
    ((uint2*)(g_xlo + (size_t)r * EE))[tid] = ul;
}

// ---------------- launch -----------------------------------------------------
extern "C" void kernel_launch(void* const* d_in, const int* in_sizes, int n_in,
                              void* d_out, int out_size)
{
    const float* x    = (const float*)d_in[0];
    // d_in[1] = attn_mask (pure causal, implemented analytically)
    const float* cosT = (const float*)d_in[2];
    const float* sinT = (const float*)d_in[3];
    const float* Wq   = (const float*)d_in[4];
    const float* bq   = (const float*)d_in[5];
    const float* Wk   = (const float*)d_in[6];
    const float* bk   = (const float*)d_in[7];
    const float* Wv   = (const float*)d_in[8];
    const float* bv   = (const float*)d_in[9];
    const float* Wo   = (const float*)d_in[10];
    const float* nw   = (const float*)d_in[11];

    float *pQ, *pK;
    __nv_bfloat16 *pxh, *pxl, *pVhi, *pVlo;
    __nv_bfloat16 *pwqh, *pwql, *pwkh, *pwkl, *pwvh, *pwvl, *pwoh, *pwol;
    cudaGetSymbolAddress((void**)&pQ, g_Q);
    cudaGetSymbolAddress((void**)&pK, g_K);
    cudaGetSymbolAddress((void**)&pxh, g_xhi);
    cudaGetSymbolAddress((void**)&pxl, g_xlo);
    cudaGetSymbolAddress((void**)&pVhi, g_Vhi);
    cudaGetSymbolAddress((void**)&pVlo, g_Vlo);
    cudaGetSymbolAddress((void**)&pwqh, g_wqhi);
    cudaGetSymbolAddress((void**)&pwql, g_wqlo);
    cudaGetSymbolAddress((void**)&pwkh, g_wkhi);
    cudaGetSymbolAddress((void**)&pwkl, g_wklo);
    cudaGetSymbolAddress((void**)&pwvh, g_wvhi);
    cudaGetSymbolAddress((void**)&pwvl, g_wvlo);
    cudaGetSymbolAddress((void**)&pwoh, g_wohi);
    cudaGetSymbolAddress((void**)&pwol, g_wolo);

    cudaFuncSetAttribute(gemm_mma<0>, cudaFuncAttributeMaxDynamicSharedMemorySize, G_SMEM);
    cudaFuncSetAttribute(gemm_mma<1>, cudaFuncAttributeMaxDynamicSharedMemorySize, G_SMEM);
    cudaFuncSetAttribute(gemm_mma<2>, cudaFuncAttributeMaxDynamicSharedMemorySize, G_SMEM);
    cudaFuncSetAttribute(attn_mma,   cudaFuncAttributeMaxDynamicSharedMemorySize, ATT_SMEM);

    const int n4x = MM * EE / 4;   // 1,048,576
    const int n4w = EE * EE / 4;   // 262,144
    dim3 ggrid(EE/128, MM/64);     // (8, 64) = 512 CTAs

    cvt_hilo<<<n4x/256, 256>>>(x, pxh, pxl, n4x);
    cvt_w4<<<n4w/256, 256>>>(Wq, Wk, Wv, Wo);

    gemm_mma<1><<<ggrid, 128, G_SMEM>>>(pxh, pxl, pwqh, pwql, bq, pQ, nullptr, nullptr);
    gemm_mma<1><<<ggrid, 128, G_SMEM>>>(pxh, pxl, pwkh, pwkl, bk, pK, nullptr, nullptr);
    gemm_mma<2><<<ggrid, 128, G_SMEM>>>(pxh, pxl, pwvh, pwvl, bv, nullptr, pVhi, pVlo);

    rope_cvt<<<(BB*HH*SQ*32)/256, 256>>>(cosT, sinT);

    attn_mma<<<dim3(SQ/128, BB*HH), 256, ATT_SMEM>>>();

    rms_cvt<<<MM, 256>>>(nw);

    gemm_mma<0><<<ggrid, 128, G_SMEM>>>(pxh, pxl, pwoh, pwol, nullptr, (float*)d_out, nullptr, nullptr);
}